// round 1
// baseline (speedup 1.0000x reference)
#include <cuda_runtime.h>
#include <math.h>

// Problem constants (fixed shapes from reference)
#define BATCH 16
#define CIN   512
#define C1    256
#define HW    4096
#define INV_SQRT_HW (1.0f/64.0f)

// Tiling
#define BM 128
#define BN 128
#define BK 16
#define NTHREADS 256

// Split-K for the energy GEMM (K=4096 -> 4 slices of 1024)
#define KSPLIT 4
#define KCHUNK (HW / KSPLIT)

// Scratch (allocation-free rule: __device__ globals)
__device__ __align__(16) float g_q  [(size_t)BATCH * C1 * HW];          // 64 MiB
__device__ __align__(16) float g_ep [(size_t)KSPLIT * BATCH * C1 * CIN]; // 32 MiB partial energies
__device__ __align__(16) float g_att[(size_t)BATCH * C1 * CIN];          // 8 MiB

// ---------------------------------------------------------------------------
// GEMM 1: q[b][o][n] = sum_c W[o][c] * x[b][c][n] + bias[o]
// A = W (256x512 row-major, shared across b), B = x_b (512x4096), C = g_q
// grid: (HW/BN, C1/BM, BATCH)
// ---------------------------------------------------------------------------
__global__ __launch_bounds__(NTHREADS) void gemm_proj(
    const float* __restrict__ W, const float* __restrict__ x,
    const float* __restrict__ bias)
{
    const int b  = blockIdx.z;
    const int m0 = blockIdx.y * BM;
    const int n0 = blockIdx.x * BN;
    const float* A = W;                       // lda = CIN
    const float* B = x + (size_t)b * CIN * HW; // ldb = HW
    float*       Cp = g_q + (size_t)b * C1 * HW;

    __shared__ __align__(16) float As[BK * BM];
    __shared__ __align__(16) float Bs[BK * BN];

    const int tid = threadIdx.x;
    const int tx = tid & 15;     // 0..15 -> n
    const int ty = tid >> 4;     // 0..15 -> m
    float acc[8][8];
    #pragma unroll
    for (int i = 0; i < 8; ++i)
        #pragma unroll
        for (int j = 0; j < 8; ++j) acc[i][j] = 0.f;

    for (int k0 = 0; k0 < CIN; k0 += BK) {
        // A tile (BM x BK), store transposed As[k][m]
        #pragma unroll
        for (int i = 0; i < 2; ++i) {
            int f  = tid + i * NTHREADS;       // 0..511
            int m  = f >> 2;                   // 4 float4 per row
            int k4 = (f & 3) * 4;
            float4 v = *reinterpret_cast<const float4*>(&A[(m0 + m) * CIN + k0 + k4]);
            As[(k4 + 0) * BM + m] = v.x;
            As[(k4 + 1) * BM + m] = v.y;
            As[(k4 + 2) * BM + m] = v.z;
            As[(k4 + 3) * BM + m] = v.w;
        }
        // B tile (BK x BN), direct Bs[k][n]
        #pragma unroll
        for (int i = 0; i < 2; ++i) {
            int f  = tid + i * NTHREADS;
            int k  = f >> 5;                   // 32 float4 per row
            int n4 = (f & 31) * 4;
            float4 v = *reinterpret_cast<const float4*>(&B[(k0 + k) * HW + n0 + n4]);
            *reinterpret_cast<float4*>(&Bs[k * BN + n4]) = v;
        }
        __syncthreads();
        #pragma unroll
        for (int k = 0; k < BK; ++k) {
            float a[8], bb[8];
            #pragma unroll
            for (int i = 0; i < 8; ++i) a[i]  = As[k * BM + ty * 8 + i];
            #pragma unroll
            for (int j = 0; j < 8; ++j) bb[j] = Bs[k * BN + tx * 8 + j];
            #pragma unroll
            for (int i = 0; i < 8; ++i)
                #pragma unroll
                for (int j = 0; j < 8; ++j) acc[i][j] += a[i] * bb[j];
        }
        __syncthreads();
    }
    #pragma unroll
    for (int i = 0; i < 8; ++i) {
        int m = m0 + ty * 8 + i;
        float bz = bias[m];
        #pragma unroll
        for (int j4 = 0; j4 < 2; ++j4) {
            float4 o;
            o.x = acc[i][j4 * 4 + 0] + bz;
            o.y = acc[i][j4 * 4 + 1] + bz;
            o.z = acc[i][j4 * 4 + 2] + bz;
            o.w = acc[i][j4 * 4 + 3] + bz;
            *reinterpret_cast<float4*>(&Cp[(size_t)m * HW + n0 + tx * 8 + j4 * 4]) = o;
        }
    }
}

// ---------------------------------------------------------------------------
// GEMM 2 (NT, split-K): ep[ks][b][qq][c] = sum_{n in slice} q[b][qq][n]*x[b][c][n]
// grid: (CIN/BN, C1/BM, BATCH*KSPLIT)
// ---------------------------------------------------------------------------
__global__ __launch_bounds__(NTHREADS) void gemm_energy(const float* __restrict__ x)
{
    const int z  = blockIdx.z;
    const int b  = z >> 2;
    const int ks = z & 3;
    const int m0 = blockIdx.y * BM;
    const int n0 = blockIdx.x * BN;         // c dimension
    const int kb = ks * KCHUNK;

    const float* A = g_q + (size_t)b * C1 * HW;   // lda = HW
    const float* B = x   + (size_t)b * CIN * HW;  // B[c][n], ldb = HW
    float* Cp = g_ep + ((size_t)(ks * BATCH + b)) * C1 * CIN;

    __shared__ __align__(16) float As[BK * BM];
    __shared__ __align__(16) float Bs[BK * BN];

    const int tid = threadIdx.x;
    const int tx = tid & 15;
    const int ty = tid >> 4;
    float acc[8][8];
    #pragma unroll
    for (int i = 0; i < 8; ++i)
        #pragma unroll
        for (int j = 0; j < 8; ++j) acc[i][j] = 0.f;

    for (int k0 = kb; k0 < kb + KCHUNK; k0 += BK) {
        #pragma unroll
        for (int i = 0; i < 2; ++i) {
            int f  = tid + i * NTHREADS;
            int m  = f >> 2;
            int k4 = (f & 3) * 4;
            float4 v = *reinterpret_cast<const float4*>(&A[(size_t)(m0 + m) * HW + k0 + k4]);
            As[(k4 + 0) * BM + m] = v.x;
            As[(k4 + 1) * BM + m] = v.y;
            As[(k4 + 2) * BM + m] = v.z;
            As[(k4 + 3) * BM + m] = v.w;
        }
        // B tile: rows are c (N dim), cols are n (K dim) -> transpose into Bs[k][c]
        #pragma unroll
        for (int i = 0; i < 2; ++i) {
            int f  = tid + i * NTHREADS;
            int n  = f >> 2;
            int k4 = (f & 3) * 4;
            float4 v = *reinterpret_cast<const float4*>(&B[(size_t)(n0 + n) * HW + k0 + k4]);
            Bs[(k4 + 0) * BN + n] = v.x;
            Bs[(k4 + 1) * BN + n] = v.y;
            Bs[(k4 + 2) * BN + n] = v.z;
            Bs[(k4 + 3) * BN + n] = v.w;
        }
        __syncthreads();
        #pragma unroll
        for (int k = 0; k < BK; ++k) {
            float a[8], bb[8];
            #pragma unroll
            for (int i = 0; i < 8; ++i) a[i]  = As[k * BM + ty * 8 + i];
            #pragma unroll
            for (int j = 0; j < 8; ++j) bb[j] = Bs[k * BN + tx * 8 + j];
            #pragma unroll
            for (int i = 0; i < 8; ++i)
                #pragma unroll
                for (int j = 0; j < 8; ++j) acc[i][j] += a[i] * bb[j];
        }
        __syncthreads();
    }
    #pragma unroll
    for (int i = 0; i < 8; ++i) {
        int m = m0 + ty * 8 + i;
        #pragma unroll
        for (int j4 = 0; j4 < 2; ++j4) {
            float4 o;
            o.x = acc[i][j4 * 4 + 0];
            o.y = acc[i][j4 * 4 + 1];
            o.z = acc[i][j4 * 4 + 2];
            o.w = acc[i][j4 * 4 + 3];
            *reinterpret_cast<float4*>(&Cp[(size_t)m * CIN + n0 + tx * 8 + j4 * 4]) = o;
        }
    }
}

// ---------------------------------------------------------------------------
// Softmax over c=512: reduce 4 split-K partials, scale by 1/64, softmax row.
// grid: BATCH*C1 blocks of 128 threads (each thread owns one float4 = 4 c's)
// ---------------------------------------------------------------------------
__global__ __launch_bounds__(128) void softmax_rows()
{
    const int row = blockIdx.x;              // b*C1 + qq
    const int tid = threadIdx.x;
    const size_t base = (size_t)row * CIN + tid * 4;
    const size_t kstride = (size_t)BATCH * C1 * CIN;

    float4 v0 = *reinterpret_cast<const float4*>(&g_ep[base]);
    float4 v1 = *reinterpret_cast<const float4*>(&g_ep[base + kstride]);
    float4 v2 = *reinterpret_cast<const float4*>(&g_ep[base + 2 * kstride]);
    float4 v3 = *reinterpret_cast<const float4*>(&g_ep[base + 3 * kstride]);
    float v[4];
    v[0] = (v0.x + v1.x + v2.x + v3.x) * INV_SQRT_HW;
    v[1] = (v0.y + v1.y + v2.y + v3.y) * INV_SQRT_HW;
    v[2] = (v0.z + v1.z + v2.z + v3.z) * INV_SQRT_HW;
    v[3] = (v0.w + v1.w + v2.w + v3.w) * INV_SQRT_HW;

    float m = fmaxf(fmaxf(v[0], v[1]), fmaxf(v[2], v[3]));
    #pragma unroll
    for (int off = 16; off > 0; off >>= 1)
        m = fmaxf(m, __shfl_xor_sync(0xffffffffu, m, off));
    __shared__ float red[4];
    const int lane = tid & 31, wid = tid >> 5;
    if (lane == 0) red[wid] = m;
    __syncthreads();
    m = fmaxf(fmaxf(red[0], red[1]), fmaxf(red[2], red[3]));
    __syncthreads();

    float e[4], s = 0.f;
    #pragma unroll
    for (int i = 0; i < 4; ++i) { e[i] = expf(v[i] - m); s += e[i]; }
    #pragma unroll
    for (int off = 16; off > 0; off >>= 1)
        s += __shfl_xor_sync(0xffffffffu, s, off);
    if (lane == 0) red[wid] = s;
    __syncthreads();
    s = red[0] + red[1] + red[2] + red[3];
    const float inv = 1.0f / s;

    float4 o;
    o.x = e[0] * inv; o.y = e[1] * inv; o.z = e[2] * inv; o.w = e[3] * inv;
    *reinterpret_cast<float4*>(&g_att[base]) = o;
}

// ---------------------------------------------------------------------------
// GEMM 3 (NN): out[b][qq][n] = gamma * sum_c att[b][qq][c]*x[b][c][n] + q[b][qq][n]
// grid: (HW/BN, C1/BM, BATCH)
// ---------------------------------------------------------------------------
__global__ __launch_bounds__(NTHREADS) void gemm_out(
    const float* __restrict__ x, const float* __restrict__ gamma,
    float* __restrict__ out)
{
    const int b  = blockIdx.z;
    const int m0 = blockIdx.y * BM;
    const int n0 = blockIdx.x * BN;
    const float* A = g_att + (size_t)b * C1 * CIN;  // lda = CIN
    const float* B = x + (size_t)b * CIN * HW;      // ldb = HW
    const float* Q = g_q + (size_t)b * C1 * HW;
    float* Cp = out + (size_t)b * C1 * HW;

    __shared__ __align__(16) float As[BK * BM];
    __shared__ __align__(16) float Bs[BK * BN];

    const int tid = threadIdx.x;
    const int tx = tid & 15;
    const int ty = tid >> 4;
    float acc[8][8];
    #pragma unroll
    for (int i = 0; i < 8; ++i)
        #pragma unroll
        for (int j = 0; j < 8; ++j) acc[i][j] = 0.f;

    for (int k0 = 0; k0 < CIN; k0 += BK) {
        #pragma unroll
        for (int i = 0; i < 2; ++i) {
            int f  = tid + i * NTHREADS;
            int m  = f >> 2;
            int k4 = (f & 3) * 4;
            float4 v = *reinterpret_cast<const float4*>(&A[(m0 + m) * CIN + k0 + k4]);
            As[(k4 + 0) * BM + m] = v.x;
            As[(k4 + 1) * BM + m] = v.y;
            As[(k4 + 2) * BM + m] = v.z;
            As[(k4 + 3) * BM + m] = v.w;
        }
        #pragma unroll
        for (int i = 0; i < 2; ++i) {
            int f  = tid + i * NTHREADS;
            int k  = f >> 5;
            int n4 = (f & 31) * 4;
            float4 v = *reinterpret_cast<const float4*>(&B[(k0 + k) * HW + n0 + n4]);
            *reinterpret_cast<float4*>(&Bs[k * BN + n4]) = v;
        }
        __syncthreads();
        #pragma unroll
        for (int k = 0; k < BK; ++k) {
            float a[8], bb[8];
            #pragma unroll
            for (int i = 0; i < 8; ++i) a[i]  = As[k * BM + ty * 8 + i];
            #pragma unroll
            for (int j = 0; j < 8; ++j) bb[j] = Bs[k * BN + tx * 8 + j];
            #pragma unroll
            for (int i = 0; i < 8; ++i)
                #pragma unroll
                for (int j = 0; j < 8; ++j) acc[i][j] += a[i] * bb[j];
        }
        __syncthreads();
    }
    const float g = __ldg(gamma);
    #pragma unroll
    for (int i = 0; i < 8; ++i) {
        int m = m0 + ty * 8 + i;
        #pragma unroll
        for (int j4 = 0; j4 < 2; ++j4) {
            const size_t idx = (size_t)m * HW + n0 + tx * 8 + j4 * 4;
            float4 qv = *reinterpret_cast<const float4*>(&Q[idx]);
            float4 o;
            o.x = g * acc[i][j4 * 4 + 0] + qv.x;
            o.y = g * acc[i][j4 * 4 + 1] + qv.y;
            o.z = g * acc[i][j4 * 4 + 2] + qv.z;
            o.w = g * acc[i][j4 * 4 + 3] + qv.w;
            *reinterpret_cast<float4*>(&Cp[idx]) = o;
        }
    }
}

// ---------------------------------------------------------------------------
extern "C" void kernel_launch(void* const* d_in, const int* in_sizes, int n_in,
                              void* d_out, int out_size)
{
    const float* x     = (const float*)d_in[0];  // (16,512,64,64)
    const float* convw = (const float*)d_in[1];  // (256,512,1,1)
    const float* convb = (const float*)d_in[2];  // (256,)
    const float* gamma = (const float*)d_in[3];  // (1,)
    float* out = (float*)d_out;                  // (16,256,64,64)

    gemm_proj  <<<dim3(HW / BN,  C1 / BM, BATCH),          NTHREADS>>>(convw, x, convb);
    gemm_energy<<<dim3(CIN / BN, C1 / BM, BATCH * KSPLIT), NTHREADS>>>(x);
    softmax_rows<<<BATCH * C1, 128>>>();
    gemm_out   <<<dim3(HW / BN,  C1 / BM, BATCH),          NTHREADS>>>(x, gamma, out);
}

// round 2
// speedup vs baseline: 1.0496x; 1.0496x over previous
#include <cuda_runtime.h>
#include <math.h>

// Problem constants (fixed shapes from reference)
#define BATCH 16
#define CIN   512
#define C1    256
#define HW    4096
#define INV_SQRT_HW (1.0f/64.0f)

// Tiling
#define BM 128
#define BN 128
#define BK 16
#define NTHREADS 256

// Split-K for the energy GEMM (K=4096 -> 4 slices of 1024)
#define KSPLIT 4
#define KCHUNK (HW / KSPLIT)

typedef unsigned long long u64;

// Packed f32x2 FMA: d = a*b + d (two fp32 lanes per instruction, sm_100+)
__device__ __forceinline__ void ffma2(u64& d, u64 a, u64 b) {
    asm("fma.rn.f32x2 %0, %1, %2, %0;" : "+l"(d) : "l"(a), "l"(b));
}
__device__ __forceinline__ u64 pack2(float x) {
    u64 r; asm("mov.b64 %0, {%1, %1};" : "=l"(r) : "f"(x)); return r;
}
__device__ __forceinline__ float2 unpack2(u64 v) {
    float2 r; asm("mov.b64 {%0, %1}, %2;" : "=f"(r.x), "=f"(r.y) : "l"(v)); return r;
}

// Scratch (allocation-free rule: __device__ globals)
__device__ __align__(16) float g_q  [(size_t)BATCH * C1 * HW];           // 64 MiB
__device__ __align__(16) float g_ep [(size_t)KSPLIT * BATCH * C1 * CIN]; // 32 MiB partial energies
__device__ __align__(16) float g_att[(size_t)BATCH * C1 * CIN];          // 8 MiB

// Shared compute core: 8x8 microtile as 8x4 packed f32x2 accumulators.
// As is [BK][BM] (k-major), Bs is [BK][BN].
#define MICRO_KERNEL(As, Bs, acc)                                              \
    _Pragma("unroll")                                                          \
    for (int k = 0; k < BK; ++k) {                                             \
        float4 a0 = *reinterpret_cast<const float4*>(&As[k * BM + ty * 8]);    \
        float4 a1 = *reinterpret_cast<const float4*>(&As[k * BM + ty * 8 + 4]);\
        ulonglong2 bq0 = *reinterpret_cast<const ulonglong2*>(&Bs[k * BN + tx * 8]);     \
        ulonglong2 bq1 = *reinterpret_cast<const ulonglong2*>(&Bs[k * BN + tx * 8 + 4]); \
        u64 b2[4] = {bq0.x, bq0.y, bq1.x, bq1.y};                              \
        u64 a2[8] = {pack2(a0.x), pack2(a0.y), pack2(a0.z), pack2(a0.w),       \
                     pack2(a1.x), pack2(a1.y), pack2(a1.z), pack2(a1.w)};      \
        _Pragma("unroll")                                                      \
        for (int i = 0; i < 8; ++i)                                            \
            _Pragma("unroll")                                                  \
            for (int j = 0; j < 4; ++j) ffma2(acc[i][j], a2[i], b2[j]);        \
    }

// ---------------------------------------------------------------------------
// GEMM 1: q[b][o][n] = sum_c W[o][c] * x[b][c][n] + bias[o]
// grid: (HW/BN, C1/BM, BATCH)
// ---------------------------------------------------------------------------
__global__ __launch_bounds__(NTHREADS, 2) void gemm_proj(
    const float* __restrict__ W, const float* __restrict__ x,
    const float* __restrict__ bias)
{
    const int b  = blockIdx.z;
    const int m0 = blockIdx.y * BM;
    const int n0 = blockIdx.x * BN;
    const float* A = W;                        // lda = CIN
    const float* B = x + (size_t)b * CIN * HW; // ldb = HW
    float*       Cp = g_q + (size_t)b * C1 * HW;

    __shared__ __align__(16) float As[BK * BM];
    __shared__ __align__(16) float Bs[BK * BN];

    const int tid = threadIdx.x;
    const int tx = tid & 15;
    const int ty = tid >> 4;
    u64 acc[8][4];
    #pragma unroll
    for (int i = 0; i < 8; ++i)
        #pragma unroll
        for (int j = 0; j < 4; ++j) acc[i][j] = 0ull;

    for (int k0 = 0; k0 < CIN; k0 += BK) {
        #pragma unroll
        for (int i = 0; i < 2; ++i) {
            int f  = tid + i * NTHREADS;
            int m  = f >> 2;
            int k4 = (f & 3) * 4;
            float4 v = *reinterpret_cast<const float4*>(&A[(m0 + m) * CIN + k0 + k4]);
            As[(k4 + 0) * BM + m] = v.x;
            As[(k4 + 1) * BM + m] = v.y;
            As[(k4 + 2) * BM + m] = v.z;
            As[(k4 + 3) * BM + m] = v.w;
        }
        #pragma unroll
        for (int i = 0; i < 2; ++i) {
            int f  = tid + i * NTHREADS;
            int k  = f >> 5;
            int n4 = (f & 31) * 4;
            float4 v = *reinterpret_cast<const float4*>(&B[(k0 + k) * HW + n0 + n4]);
            *reinterpret_cast<float4*>(&Bs[k * BN + n4]) = v;
        }
        __syncthreads();
        MICRO_KERNEL(As, Bs, acc)
        __syncthreads();
    }
    #pragma unroll
    for (int i = 0; i < 8; ++i) {
        int m = m0 + ty * 8 + i;
        float bz = bias[m];
        #pragma unroll
        for (int j4 = 0; j4 < 2; ++j4) {
            float2 p0 = unpack2(acc[i][j4 * 2 + 0]);
            float2 p1 = unpack2(acc[i][j4 * 2 + 1]);
            float4 o;
            o.x = p0.x + bz; o.y = p0.y + bz;
            o.z = p1.x + bz; o.w = p1.y + bz;
            *reinterpret_cast<float4*>(&Cp[(size_t)m * HW + n0 + tx * 8 + j4 * 4]) = o;
        }
    }
}

// ---------------------------------------------------------------------------
// GEMM 2 (NT, split-K): ep[ks][b][qq][c] = sum_{n in slice} q[b][qq][n]*x[b][c][n]
// grid: (CIN/BN, C1/BM, BATCH*KSPLIT)
// ---------------------------------------------------------------------------
__global__ __launch_bounds__(NTHREADS, 2) void gemm_energy(const float* __restrict__ x)
{
    const int z  = blockIdx.z;
    const int b  = z >> 2;
    const int ks = z & 3;
    const int m0 = blockIdx.y * BM;
    const int n0 = blockIdx.x * BN;
    const int kb = ks * KCHUNK;

    const float* A = g_q + (size_t)b * C1 * HW;
    const float* B = x   + (size_t)b * CIN * HW;
    float* Cp = g_ep + ((size_t)(ks * BATCH + b)) * C1 * CIN;

    __shared__ __align__(16) float As[BK * BM];
    __shared__ __align__(16) float Bs[BK * BN];

    const int tid = threadIdx.x;
    const int tx = tid & 15;
    const int ty = tid >> 4;
    u64 acc[8][4];
    #pragma unroll
    for (int i = 0; i < 8; ++i)
        #pragma unroll
        for (int j = 0; j < 4; ++j) acc[i][j] = 0ull;

    for (int k0 = kb; k0 < kb + KCHUNK; k0 += BK) {
        #pragma unroll
        for (int i = 0; i < 2; ++i) {
            int f  = tid + i * NTHREADS;
            int m  = f >> 2;
            int k4 = (f & 3) * 4;
            float4 v = *reinterpret_cast<const float4*>(&A[(size_t)(m0 + m) * HW + k0 + k4]);
            As[(k4 + 0) * BM + m] = v.x;
            As[(k4 + 1) * BM + m] = v.y;
            As[(k4 + 2) * BM + m] = v.z;
            As[(k4 + 3) * BM + m] = v.w;
        }
        #pragma unroll
        for (int i = 0; i < 2; ++i) {
            int f  = tid + i * NTHREADS;
            int n  = f >> 2;
            int k4 = (f & 3) * 4;
            float4 v = *reinterpret_cast<const float4*>(&B[(size_t)(n0 + n) * HW + k0 + k4]);
            Bs[(k4 + 0) * BN + n] = v.x;
            Bs[(k4 + 1) * BN + n] = v.y;
            Bs[(k4 + 2) * BN + n] = v.z;
            Bs[(k4 + 3) * BN + n] = v.w;
        }
        __syncthreads();
        MICRO_KERNEL(As, Bs, acc)
        __syncthreads();
    }
    #pragma unroll
    for (int i = 0; i < 8; ++i) {
        int m = m0 + ty * 8 + i;
        #pragma unroll
        for (int j4 = 0; j4 < 2; ++j4) {
            float2 p0 = unpack2(acc[i][j4 * 2 + 0]);
            float2 p1 = unpack2(acc[i][j4 * 2 + 1]);
            float4 o; o.x = p0.x; o.y = p0.y; o.z = p1.x; o.w = p1.y;
            *reinterpret_cast<float4*>(&Cp[(size_t)m * CIN + n0 + tx * 8 + j4 * 4]) = o;
        }
    }
}

// ---------------------------------------------------------------------------
// Softmax over c=512: reduce 4 split-K partials, scale by 1/64, softmax row.
// ---------------------------------------------------------------------------
__global__ __launch_bounds__(128) void softmax_rows()
{
    const int row = blockIdx.x;
    const int tid = threadIdx.x;
    const size_t base = (size_t)row * CIN + tid * 4;
    const size_t kstride = (size_t)BATCH * C1 * CIN;

    float4 v0 = *reinterpret_cast<const float4*>(&g_ep[base]);
    float4 v1 = *reinterpret_cast<const float4*>(&g_ep[base + kstride]);
    float4 v2 = *reinterpret_cast<const float4*>(&g_ep[base + 2 * kstride]);
    float4 v3 = *reinterpret_cast<const float4*>(&g_ep[base + 3 * kstride]);
    float v[4];
    v[0] = (v0.x + v1.x + v2.x + v3.x) * INV_SQRT_HW;
    v[1] = (v0.y + v1.y + v2.y + v3.y) * INV_SQRT_HW;
    v[2] = (v0.z + v1.z + v2.z + v3.z) * INV_SQRT_HW;
    v[3] = (v0.w + v1.w + v2.w + v3.w) * INV_SQRT_HW;

    float m = fmaxf(fmaxf(v[0], v[1]), fmaxf(v[2], v[3]));
    #pragma unroll
    for (int off = 16; off > 0; off >>= 1)
        m = fmaxf(m, __shfl_xor_sync(0xffffffffu, m, off));
    __shared__ float red[4];
    const int lane = tid & 31, wid = tid >> 5;
    if (lane == 0) red[wid] = m;
    __syncthreads();
    m = fmaxf(fmaxf(red[0], red[1]), fmaxf(red[2], red[3]));
    __syncthreads();

    float e[4], s = 0.f;
    #pragma unroll
    for (int i = 0; i < 4; ++i) { e[i] = expf(v[i] - m); s += e[i]; }
    #pragma unroll
    for (int off = 16; off > 0; off >>= 1)
        s += __shfl_xor_sync(0xffffffffu, s, off);
    if (lane == 0) red[wid] = s;
    __syncthreads();
    s = red[0] + red[1] + red[2] + red[3];
    const float inv = 1.0f / s;

    float4 o;
    o.x = e[0] * inv; o.y = e[1] * inv; o.z = e[2] * inv; o.w = e[3] * inv;
    *reinterpret_cast<float4*>(&g_att[base]) = o;
}

// ---------------------------------------------------------------------------
// GEMM 3 (NN): out[b][qq][n] = gamma * sum_c att[b][qq][c]*x[b][c][n] + q[b][qq][n]
// ---------------------------------------------------------------------------
__global__ __launch_bounds__(NTHREADS, 2) void gemm_out(
    const float* __restrict__ x, const float* __restrict__ gamma,
    float* __restrict__ out)
{
    const int b  = blockIdx.z;
    const int m0 = blockIdx.y * BM;
    const int n0 = blockIdx.x * BN;
    const float* A = g_att + (size_t)b * C1 * CIN;
    const float* B = x + (size_t)b * CIN * HW;
    const float* Q = g_q + (size_t)b * C1 * HW;
    float* Cp = out + (size_t)b * C1 * HW;

    __shared__ __align__(16) float As[BK * BM];
    __shared__ __align__(16) float Bs[BK * BN];

    const int tid = threadIdx.x;
    const int tx = tid & 15;
    const int ty = tid >> 4;
    u64 acc[8][4];
    #pragma unroll
    for (int i = 0; i < 8; ++i)
        #pragma unroll
        for (int j = 0; j < 4; ++j) acc[i][j] = 0ull;

    for (int k0 = 0; k0 < CIN; k0 += BK) {
        #pragma unroll
        for (int i = 0; i < 2; ++i) {
            int f  = tid + i * NTHREADS;
            int m  = f >> 2;
            int k4 = (f & 3) * 4;
            float4 v = *reinterpret_cast<const float4*>(&A[(m0 + m) * CIN + k0 + k4]);
            As[(k4 + 0) * BM + m] = v.x;
            As[(k4 + 1) * BM + m] = v.y;
            As[(k4 + 2) * BM + m] = v.z;
            As[(k4 + 3) * BM + m] = v.w;
        }
        #pragma unroll
        for (int i = 0; i < 2; ++i) {
            int f  = tid + i * NTHREADS;
            int k  = f >> 5;
            int n4 = (f & 31) * 4;
            float4 v = *reinterpret_cast<const float4*>(&B[(k0 + k) * HW + n0 + n4]);
            *reinterpret_cast<float4*>(&Bs[k * BN + n4]) = v;
        }
        __syncthreads();
        MICRO_KERNEL(As, Bs, acc)
        __syncthreads();
    }
    const float g = __ldg(gamma);
    #pragma unroll
    for (int i = 0; i < 8; ++i) {
        int m = m0 + ty * 8 + i;
        #pragma unroll
        for (int j4 = 0; j4 < 2; ++j4) {
            const size_t idx = (size_t)m * HW + n0 + tx * 8 + j4 * 4;
            float4 qv = *reinterpret_cast<const float4*>(&Q[idx]);
            float2 p0 = unpack2(acc[i][j4 * 2 + 0]);
            float2 p1 = unpack2(acc[i][j4 * 2 + 1]);
            float4 o;
            o.x = g * p0.x + qv.x;
            o.y = g * p0.y + qv.y;
            o.z = g * p1.x + qv.z;
            o.w = g * p1.y + qv.w;
            *reinterpret_cast<float4*>(&Cp[idx]) = o;
        }
    }
}

// ---------------------------------------------------------------------------
extern "C" void kernel_launch(void* const* d_in, const int* in_sizes, int n_in,
                              void* d_out, int out_size)
{
    const float* x     = (const float*)d_in[0];  // (16,512,64,64)
    const float* convw = (const float*)d_in[1];  // (256,512,1,1)
    const float* convb = (const float*)d_in[2];  // (256,)
    const float* gamma = (const float*)d_in[3];  // (1,)
    float* out = (float*)d_out;                  // (16,256,64,64)

    gemm_proj  <<<dim3(HW / BN,  C1 / BM, BATCH),          NTHREADS>>>(convw, x, convb);
    gemm_energy<<<dim3(CIN / BN, C1 / BM, BATCH * KSPLIT), NTHREADS>>>(x);
    softmax_rows<<<BATCH * C1, 128>>>();
    gemm_out   <<<dim3(HW / BN,  C1 / BM, BATCH),          NTHREADS>>>(x, gamma, out);
}

// round 4
// speedup vs baseline: 2.2281x; 2.1228x over previous
#include <cuda_runtime.h>
#include <cuda_fp16.h>
#include <stdint.h>
#include <math.h>

// Problem constants
#define BATCH 16
#define CIN   512
#define C1    256
#define HW    4096
#define INV_SQRT_HW (1.0f/64.0f)

// GEMM tiling
#define BM 128
#define BN 128
#define BK 32
#define NTH 256
#define SROW 40          // padded row stride in halves (80 B: bank-conflict-free)

// Split-K for energy GEMM (fills the chip: 128 -> 256 CTAs)
#define KSPLIT_E 2

// Scratch (allocation-free rule: __device__ globals)
__device__ __align__(16) float g_q  [(size_t)BATCH * C1 * HW];             // 64 MiB
__device__ __align__(16) float g_xT [(size_t)BATCH * HW * CIN];            // 128 MiB
__device__ __align__(16) float g_ep [(size_t)BATCH * KSPLIT_E * C1 * CIN]; // 16 MiB
__device__ __align__(16) float g_att[(size_t)BATCH * C1 * CIN];            // 8 MiB

// fp32 -> fp16 hi + fp16 residual, packed as half2 words
__device__ __forceinline__ void split_h(float a, float b, uint32_t& hi, uint32_t& lo) {
    __half ha = __float2half_rn(a), hb = __float2half_rn(b);
    __half la = __float2half_rn(a - __half2float(ha));
    __half lb = __float2half_rn(b - __half2float(hb));
    hi = (uint32_t)__half_as_ushort(ha) | ((uint32_t)__half_as_ushort(hb) << 16);
    lo = (uint32_t)__half_as_ushort(la) | ((uint32_t)__half_as_ushort(lb) << 16);
}
__device__ __forceinline__ uint32_t pack_h(float a, float b) {
    return (uint32_t)__half_as_ushort(__float2half_rn(a)) |
           ((uint32_t)__half_as_ushort(__float2half_rn(b)) << 16);
}

// m16n8k16 row.col f32 <- f16 x f16
__device__ __forceinline__ void mma16816(float* d, const uint32_t* a, uint32_t b0, uint32_t b1) {
    asm volatile(
        "mma.sync.aligned.m16n8k16.row.col.f32.f16.f16.f32 "
        "{%0,%1,%2,%3}, {%4,%5,%6,%7}, {%8,%9}, {%0,%1,%2,%3};"
        : "+f"(d[0]), "+f"(d[1]), "+f"(d[2]), "+f"(d[3])
        : "r"(a[0]), "r"(a[1]), "r"(a[2]), "r"(a[3]), "r"(b0), "r"(b1));
}

// ---------------------------------------------------------------------------
// Transpose: xT[b][n][c] = x[b][c][n]
// ---------------------------------------------------------------------------
__global__ __launch_bounds__(256) void transpose_x(const float* __restrict__ x)
{
    __shared__ float t[32][33];
    const int b = blockIdx.z;
    const int n0 = blockIdx.x * 32, c0 = blockIdx.y * 32;
    const int tx = threadIdx.x, ty = threadIdx.y;   // (32, 8)
    const float* xs = x + (size_t)b * CIN * HW;
    float* xt = g_xT + (size_t)b * HW * CIN;
    #pragma unroll
    for (int i = 0; i < 4; ++i)
        t[ty + i * 8][tx] = xs[(size_t)(c0 + ty + i * 8) * HW + n0 + tx];
    __syncthreads();
    #pragma unroll
    for (int i = 0; i < 4; ++i)
        xt[(size_t)(n0 + ty + i * 8) * CIN + c0 + tx] = t[tx][ty + i * 8];
}

// ---------------------------------------------------------------------------
// NT GEMM, fp32-emulated via fp16 2-pass: D[m][n] = sum_k A[m][k]*B[n][k]
// EPI 0: +bias[m]   EPI 1: raw partial   EPI 2: gamma*acc + res[m][n]
// grid: (N/BN, M/BM, BATCH*zdiv); z -> batch=z/zdiv, kslice=z%zdiv
// ---------------------------------------------------------------------------
template<int EPI>
__global__ __launch_bounds__(NTH, 2) void gemm_mma(
    const float* __restrict__ A, size_t sA, int lda,
    const float* __restrict__ B, size_t sB, int ldb,
    float* __restrict__ C, size_t sC, int ldc,
    int K, int zdiv,
    const float* __restrict__ aux, size_t sAux,
    const float* __restrict__ gamma)
{
    __shared__ __half sAhi[BM * SROW];
    __shared__ __half sAlo[BM * SROW];
    __shared__ __half sBhi[BN * SROW];

    const int tid  = threadIdx.x;
    const int z    = blockIdx.z;
    const int b    = z / zdiv;
    const int kbase = (z % zdiv) * K;
    const int m0 = blockIdx.y * BM;
    const int n0 = blockIdx.x * BN;

    const float* Ab = A + (size_t)b * sA + kbase;
    const float* Bb = B + (size_t)b * sB + kbase;
    float*       Cb = C + (size_t)z * sC;

    const int wid = tid >> 5, lane = tid & 31;
    const int wm = (wid & 3) * 32;       // warp m-origin (4 warps down)
    const int wn = (wid >> 2) * 64;      // warp n-origin (2 warps across)
    const int g  = lane >> 2;            // group row
    const int t2 = (lane & 3) * 2;       // k/col pair offset

    float acc[2][8][4];
    #pragma unroll
    for (int mi = 0; mi < 2; ++mi)
        #pragma unroll
        for (int ni = 0; ni < 8; ++ni)
            #pragma unroll
            for (int r = 0; r < 4; ++r) acc[mi][ni][r] = 0.f;

    const int nst = K / BK;
    for (int s = 0; s < nst; ++s) {
        const int k0 = s * BK;
        __syncthreads();
        // ---- fill: A hi/lo + B hi (128x32 fp32 each) ----
        #pragma unroll
        for (int i = 0; i < 4; ++i) {
            int f  = tid + i * NTH;        // 0..1023
            int m  = f >> 3;
            int k4 = (f & 7) * 4;
            float4 va = *reinterpret_cast<const float4*>(&Ab[(size_t)(m0 + m) * lda + k0 + k4]);
            uint32_t h01, l01, h23, l23;
            split_h(va.x, va.y, h01, l01);
            split_h(va.z, va.w, h23, l23);
            *reinterpret_cast<uint2*>(&sAhi[m * SROW + k4]) = make_uint2(h01, h23);
            *reinterpret_cast<uint2*>(&sAlo[m * SROW + k4]) = make_uint2(l01, l23);
            float4 vb = *reinterpret_cast<const float4*>(&Bb[(size_t)(n0 + m) * ldb + k0 + k4]);
            *reinterpret_cast<uint2*>(&sBhi[m * SROW + k4]) =
                make_uint2(pack_h(vb.x, vb.y), pack_h(vb.z, vb.w));
        }
        __syncthreads();
        // ---- compute: 2 ksteps of 16 ----
        #pragma unroll
        for (int kk = 0; kk < BK; kk += 16) {
            uint32_t ah[2][4], al[2][4];
            #pragma unroll
            for (int mi = 0; mi < 2; ++mi) {
                int r = wm + mi * 16 + g;
                ah[mi][0] = *reinterpret_cast<const uint32_t*>(&sAhi[r * SROW + kk + t2]);
                ah[mi][1] = *reinterpret_cast<const uint32_t*>(&sAhi[(r + 8) * SROW + kk + t2]);
                ah[mi][2] = *reinterpret_cast<const uint32_t*>(&sAhi[r * SROW + kk + t2 + 8]);
                ah[mi][3] = *reinterpret_cast<const uint32_t*>(&sAhi[(r + 8) * SROW + kk + t2 + 8]);
                al[mi][0] = *reinterpret_cast<const uint32_t*>(&sAlo[r * SROW + kk + t2]);
                al[mi][1] = *reinterpret_cast<const uint32_t*>(&sAlo[(r + 8) * SROW + kk + t2]);
                al[mi][2] = *reinterpret_cast<const uint32_t*>(&sAlo[r * SROW + kk + t2 + 8]);
                al[mi][3] = *reinterpret_cast<const uint32_t*>(&sAlo[(r + 8) * SROW + kk + t2 + 8]);
            }
            #pragma unroll
            for (int ni = 0; ni < 8; ++ni) {
                int n = wn + ni * 8 + g;
                uint32_t b0 = *reinterpret_cast<const uint32_t*>(&sBhi[n * SROW + kk + t2]);
                uint32_t b1 = *reinterpret_cast<const uint32_t*>(&sBhi[n * SROW + kk + t2 + 8]);
                #pragma unroll
                for (int mi = 0; mi < 2; ++mi) {
                    mma16816(acc[mi][ni], ah[mi], b0, b1);
                    mma16816(acc[mi][ni], al[mi], b0, b1);
                }
            }
        }
    }

    // ---- epilogue ----
    const float gm = (EPI == 2) ? __ldg(gamma) : 0.f;
    const float* Rb = (EPI == 2) ? aux + (size_t)b * sAux : aux;
    #pragma unroll
    for (int mi = 0; mi < 2; ++mi) {
        int row = m0 + wm + mi * 16 + g;
        #pragma unroll
        for (int ni = 0; ni < 8; ++ni) {
            int col = n0 + wn + ni * 8 + t2;
            float2 v0 = make_float2(acc[mi][ni][0], acc[mi][ni][1]);
            float2 v1 = make_float2(acc[mi][ni][2], acc[mi][ni][3]);
            if (EPI == 0) {
                float b0 = Rb[row], b1 = Rb[row + 8];
                v0.x += b0; v0.y += b0;
                v1.x += b1; v1.y += b1;
            } else if (EPI == 2) {
                float2 q0 = *reinterpret_cast<const float2*>(&Rb[(size_t)row * ldc + col]);
                float2 q1 = *reinterpret_cast<const float2*>(&Rb[(size_t)(row + 8) * ldc + col]);
                v0.x = gm * v0.x + q0.x; v0.y = gm * v0.y + q0.y;
                v1.x = gm * v1.x + q1.x; v1.y = gm * v1.y + q1.y;
            }
            *reinterpret_cast<float2*>(&Cb[(size_t)row * ldc + col]) = v0;
            *reinterpret_cast<float2*>(&Cb[(size_t)(row + 8) * ldc + col]) = v1;
        }
    }
}

// ---------------------------------------------------------------------------
// Softmax over c=512: reduce KSPLIT_E partials, scale 1/64, softmax -> g_att
// ---------------------------------------------------------------------------
__global__ __launch_bounds__(128) void softmax_rows()
{
    const int row = blockIdx.x;              // b*C1 + m
    const int b   = row / C1;
    const int m   = row % C1;
    const int tid = threadIdx.x;
    const size_t p0 = ((size_t)b * KSPLIT_E) * C1 * CIN + (size_t)m * CIN + tid * 4;
    const size_t pk = (size_t)C1 * CIN;

    float4 a0 = *reinterpret_cast<const float4*>(&g_ep[p0]);
    float4 a1 = *reinterpret_cast<const float4*>(&g_ep[p0 + pk]);
    float v[4];
    v[0] = (a0.x + a1.x) * INV_SQRT_HW;
    v[1] = (a0.y + a1.y) * INV_SQRT_HW;
    v[2] = (a0.z + a1.z) * INV_SQRT_HW;
    v[3] = (a0.w + a1.w) * INV_SQRT_HW;

    float mx = fmaxf(fmaxf(v[0], v[1]), fmaxf(v[2], v[3]));
    #pragma unroll
    for (int off = 16; off > 0; off >>= 1)
        mx = fmaxf(mx, __shfl_xor_sync(0xffffffffu, mx, off));
    __shared__ float red[4];
    const int lane = tid & 31, wid = tid >> 5;
    if (lane == 0) red[wid] = mx;
    __syncthreads();
    mx = fmaxf(fmaxf(red[0], red[1]), fmaxf(red[2], red[3]));
    __syncthreads();

    float e[4], s = 0.f;
    #pragma unroll
    for (int i = 0; i < 4; ++i) { e[i] = expf(v[i] - mx); s += e[i]; }
    #pragma unroll
    for (int off = 16; off > 0; off >>= 1)
        s += __shfl_xor_sync(0xffffffffu, s, off);
    if (lane == 0) red[wid] = s;
    __syncthreads();
    s = red[0] + red[1] + red[2] + red[3];
    const float inv = 1.0f / s;

    float4 o;
    o.x = e[0] * inv; o.y = e[1] * inv; o.z = e[2] * inv; o.w = e[3] * inv;
    *reinterpret_cast<float4*>(&g_att[(size_t)row * CIN + tid * 4]) = o;
}

// ---------------------------------------------------------------------------
extern "C" void kernel_launch(void* const* d_in, const int* in_sizes, int n_in,
                              void* d_out, int out_size)
{
    const float* x     = (const float*)d_in[0];  // (16,512,64,64)
    const float* convw = (const float*)d_in[1];  // (256,512,1,1)
    const float* convb = (const float*)d_in[2];  // (256,)
    const float* gamma = (const float*)d_in[3];  // (1,)
    float* out = (float*)d_out;                  // (16,256,64,64)

    float* qptr  = nullptr; cudaGetSymbolAddress((void**)&qptr,  g_q);
    float* xtptr = nullptr; cudaGetSymbolAddress((void**)&xtptr, g_xT);
    float* eptr  = nullptr; cudaGetSymbolAddress((void**)&eptr,  g_ep);
    float* aptr  = nullptr; cudaGetSymbolAddress((void**)&aptr,  g_att);

    transpose_x<<<dim3(HW / 32, CIN / 32, BATCH), dim3(32, 8)>>>(x);

    // proj: q = W x + b     (M=C1, N=HW, K=CIN)  A=W (shared), B=xT
    gemm_mma<0><<<dim3(HW / BN, C1 / BM, BATCH), NTH>>>(
        convw, 0, CIN, xtptr, (size_t)HW * CIN, CIN,
        qptr, (size_t)C1 * HW, HW, CIN, 1, convb, 0, nullptr);

    // energy partials: e = q x^T  (M=C1, N=CIN, K=HW split in 2)
    gemm_mma<1><<<dim3(CIN / BN, C1 / BM, BATCH * KSPLIT_E), NTH>>>(
        qptr, (size_t)C1 * HW, HW, x, (size_t)CIN * HW, HW,
        eptr, (size_t)C1 * CIN, CIN, HW / KSPLIT_E, KSPLIT_E, nullptr, 0, nullptr);

    softmax_rows<<<BATCH * C1, 128>>>();

    // out: gamma*(att x) + q  (M=C1, N=HW, K=CIN)  A=att, B=xT
    gemm_mma<2><<<dim3(HW / BN, C1 / BM, BATCH), NTH>>>(
        aptr, (size_t)C1 * CIN, CIN, xtptr, (size_t)HW * CIN, CIN,
        out, (size_t)C1 * HW, HW, CIN, 1, qptr, (size_t)C1 * HW, gamma);
}

// round 5
// speedup vs baseline: 3.0902x; 1.3869x over previous
#include <cuda_runtime.h>
#include <cuda_fp16.h>
#include <stdint.h>
#include <math.h>

// Problem constants
#define BATCH 16
#define CIN   512
#define C1    256
#define HW    4096
#define INV_SQRT_HW (1.0f/64.0f)

// GEMM tiling
#define BM 128
#define BN 128
#define BK 32
#define NTH 256
#define SROW 40                 // padded row stride in halves (80 B)

// SMEM stage layout (bytes)
#define TILE_B (BM * SROW * 2)  // 10240
#define T_AHI 0
#define T_ALO TILE_B
#define T_BHI (2 * TILE_B)
#define STAGE_B (3 * TILE_B)    // 30720
#define DYN_SMEM (2 * STAGE_B)  // 61440

#define KSPLIT_E 2

// Scratch (allocation-free rule: __device__ globals)
__device__ __align__(16) float  g_q   [(size_t)BATCH * C1 * HW];             // fp32 residual
__device__ __align__(16) __half g_q_hi[(size_t)BATCH * C1 * HW];
__device__ __align__(16) __half g_q_lo[(size_t)BATCH * C1 * HW];
__device__ __align__(16) __half g_x_hi[(size_t)BATCH * CIN * HW];
__device__ __align__(16) __half g_xT_hi[(size_t)BATCH * HW * CIN];
__device__ __align__(16) __half g_w_hi[(size_t)C1 * CIN];
__device__ __align__(16) __half g_w_lo[(size_t)C1 * CIN];
__device__ __align__(16) float  g_ep  [(size_t)BATCH * KSPLIT_E * C1 * CIN];
__device__ __align__(16) __half g_a_hi[(size_t)BATCH * C1 * CIN];
__device__ __align__(16) __half g_a_lo[(size_t)BATCH * C1 * CIN];

// ---------------- helpers ----------------
__device__ __forceinline__ uint32_t smem_u32(const void* p) {
    uint32_t a;
    asm("{ .reg .u64 t; cvta.to.shared.u64 t, %1; cvt.u32.u64 %0, t; }" : "=r"(a) : "l"(p));
    return a;
}
__device__ __forceinline__ void cpasync16(uint32_t dst, const void* src) {
    asm volatile("cp.async.cg.shared.global [%0], [%1], 16;" :: "r"(dst), "l"(src) : "memory");
}
#define CP_COMMIT() asm volatile("cp.async.commit_group;" ::: "memory")
#define CP_WAIT(n)  asm volatile("cp.async.wait_group %0;" :: "n"(n) : "memory")

__device__ __forceinline__ void mma16816(float* d, const uint32_t* a, uint32_t b0, uint32_t b1) {
    asm volatile(
        "mma.sync.aligned.m16n8k16.row.col.f32.f16.f16.f32 "
        "{%0,%1,%2,%3}, {%4,%5,%6,%7}, {%8,%9}, {%0,%1,%2,%3};"
        : "+f"(d[0]), "+f"(d[1]), "+f"(d[2]), "+f"(d[3])
        : "r"(a[0]), "r"(a[1]), "r"(a[2]), "r"(a[3]), "r"(b0), "r"(b1));
}
__device__ __forceinline__ void split1(float v, __half& hi, __half& lo) {
    hi = __float2half_rn(v);
    lo = __float2half_rn(v - __half2float(hi));
}

// ---------------------------------------------------------------------------
// prep_x: x fp32 -> x_hi (same layout) + xT_hi (transposed), fp16
// ---------------------------------------------------------------------------
__global__ __launch_bounds__(256) void prep_x(const float* __restrict__ x)
{
    __shared__ float t[32][33];
    const int b = blockIdx.z;
    const int n0 = blockIdx.x * 32, c0 = blockIdx.y * 32;
    const int tx = threadIdx.x, ty = threadIdx.y;   // (32, 8)
    const float* xs = x + (size_t)b * CIN * HW;
    __half* xh  = g_x_hi  + (size_t)b * CIN * HW;
    __half* xth = g_xT_hi + (size_t)b * HW * CIN;
    #pragma unroll
    for (int i = 0; i < 4; ++i) {
        float v = xs[(size_t)(c0 + ty + i * 8) * HW + n0 + tx];
        t[ty + i * 8][tx] = v;
        xh[(size_t)(c0 + ty + i * 8) * HW + n0 + tx] = __float2half_rn(v);
    }
    __syncthreads();
    #pragma unroll
    for (int i = 0; i < 4; ++i)
        xth[(size_t)(n0 + ty + i * 8) * CIN + c0 + tx] = __float2half_rn(t[tx][ty + i * 8]);
}

// prep_w: W fp32 -> hi/lo fp16
__global__ __launch_bounds__(256) void prep_w(const float* __restrict__ w)
{
    int f = blockIdx.x * 256 + threadIdx.x;
    if (f < C1 * CIN) {
        __half h, l; split1(w[f], h, l);
        g_w_hi[f] = h; g_w_lo[f] = l;
    }
}

// ---------------------------------------------------------------------------
// NT GEMM (fp16 2-pass, cp.async double-buffered):
//   D[m][n] = sum_k (Ahi+Alo)[m][k] * Bhi[n][k]
// EPI 0: +bias, also emit hi/lo fp16 of result
// EPI 1: raw partial
// EPI 2: gamma*acc + res[m][n]
// grid: (N/BN, M/BM, BATCH*zdiv)
// ---------------------------------------------------------------------------
template<int EPI>
__global__ __launch_bounds__(NTH, 2) void gemm_mma(
    const __half* __restrict__ Ahi, const __half* __restrict__ Alo, size_t sA, int lda,
    const __half* __restrict__ Bhi, size_t sB, int ldb,
    float* __restrict__ C, size_t sC, int ldc,
    int K, int zdiv,
    const float* __restrict__ aux, size_t sAux,
    const float* __restrict__ gamma,
    __half* __restrict__ outHi, __half* __restrict__ outLo)
{
    extern __shared__ char dyn[];
    const uint32_t sbase = smem_u32(dyn);

    const int tid  = threadIdx.x;
    const int z    = blockIdx.z;
    const int b    = z / zdiv;
    const int kbase = (z % zdiv) * K;
    const int m0 = blockIdx.y * BM;
    const int n0 = blockIdx.x * BN;

    const __half* Ah = Ahi + (size_t)b * sA + kbase;
    const __half* Al = Alo + (size_t)b * sA + kbase;
    const __half* Bh = Bhi + (size_t)b * sB + kbase;
    float*        Cb = C   + (size_t)z * sC;

    const int wid = tid >> 5, lane = tid & 31;
    const int wm = (wid & 3) * 32;
    const int wn = (wid >> 2) * 64;
    const int g  = lane >> 2;
    const int t2 = (lane & 3) * 2;

    // per-thread fill coords: 2 chunks of 16B per array per stage
    const int fr0 = tid >> 2, fc0 = tid & 3;              // f = tid
    const int fr1 = (tid + NTH) >> 2, fc1 = (tid + NTH) & 3;

    float acc[2][8][4];
    #pragma unroll
    for (int mi = 0; mi < 2; ++mi)
        #pragma unroll
        for (int ni = 0; ni < 8; ++ni)
            #pragma unroll
            for (int r = 0; r < 4; ++r) acc[mi][ni][r] = 0.f;

    const int nst = K / BK;

#define ISSUE(s) do {                                                              \
        const uint32_t sb_ = sbase + ((s) & 1) * STAGE_B;                          \
        const int k0_ = (s) * BK;                                                  \
        cpasync16(sb_ + T_AHI + fr0 * 80 + fc0 * 16, Ah + (size_t)(m0 + fr0) * lda + k0_ + fc0 * 8); \
        cpasync16(sb_ + T_AHI + fr1 * 80 + fc1 * 16, Ah + (size_t)(m0 + fr1) * lda + k0_ + fc1 * 8); \
        cpasync16(sb_ + T_ALO + fr0 * 80 + fc0 * 16, Al + (size_t)(m0 + fr0) * lda + k0_ + fc0 * 8); \
        cpasync16(sb_ + T_ALO + fr1 * 80 + fc1 * 16, Al + (size_t)(m0 + fr1) * lda + k0_ + fc1 * 8); \
        cpasync16(sb_ + T_BHI + fr0 * 80 + fc0 * 16, Bh + (size_t)(n0 + fr0) * ldb + k0_ + fc0 * 8); \
        cpasync16(sb_ + T_BHI + fr1 * 80 + fc1 * 16, Bh + (size_t)(n0 + fr1) * ldb + k0_ + fc1 * 8); \
        CP_COMMIT();                                                               \
    } while (0)

    ISSUE(0);
    for (int s = 0; s < nst; ++s) {
        if (s + 1 < nst) { ISSUE(s + 1); CP_WAIT(1); }
        else             { CP_WAIT(0); }
        __syncthreads();

        const __half* sAhi = reinterpret_cast<const __half*>(dyn + (s & 1) * STAGE_B + T_AHI);
        const __half* sAlo = reinterpret_cast<const __half*>(dyn + (s & 1) * STAGE_B + T_ALO);
        const __half* sBhi = reinterpret_cast<const __half*>(dyn + (s & 1) * STAGE_B + T_BHI);

        #pragma unroll
        for (int kk = 0; kk < BK; kk += 16) {
            uint32_t ah[2][4], al[2][4];
            #pragma unroll
            for (int mi = 0; mi < 2; ++mi) {
                int r = wm + mi * 16 + g;
                ah[mi][0] = *reinterpret_cast<const uint32_t*>(&sAhi[r * SROW + kk + t2]);
                ah[mi][1] = *reinterpret_cast<const uint32_t*>(&sAhi[(r + 8) * SROW + kk + t2]);
                ah[mi][2] = *reinterpret_cast<const uint32_t*>(&sAhi[r * SROW + kk + t2 + 8]);
                ah[mi][3] = *reinterpret_cast<const uint32_t*>(&sAhi[(r + 8) * SROW + kk + t2 + 8]);
                al[mi][0] = *reinterpret_cast<const uint32_t*>(&sAlo[r * SROW + kk + t2]);
                al[mi][1] = *reinterpret_cast<const uint32_t*>(&sAlo[(r + 8) * SROW + kk + t2]);
                al[mi][2] = *reinterpret_cast<const uint32_t*>(&sAlo[r * SROW + kk + t2 + 8]);
                al[mi][3] = *reinterpret_cast<const uint32_t*>(&sAlo[(r + 8) * SROW + kk + t2 + 8]);
            }
            #pragma unroll
            for (int ni = 0; ni < 8; ++ni) {
                int n = wn + ni * 8 + g;
                uint32_t b0 = *reinterpret_cast<const uint32_t*>(&sBhi[n * SROW + kk + t2]);
                uint32_t b1 = *reinterpret_cast<const uint32_t*>(&sBhi[n * SROW + kk + t2 + 8]);
                #pragma unroll
                for (int mi = 0; mi < 2; ++mi) {
                    mma16816(acc[mi][ni], ah[mi], b0, b1);
                    mma16816(acc[mi][ni], al[mi], b0, b1);
                }
            }
        }
        __syncthreads();
    }
#undef ISSUE

    // ---- epilogue ----
    const float gm = (EPI == 2) ? __ldg(gamma) : 0.f;
    const float* Rb = (EPI == 2) ? aux + (size_t)b * sAux : aux;
    __half* oh = (EPI == 0) ? outHi + (size_t)z * sC : nullptr;
    __half* ol = (EPI == 0) ? outLo + (size_t)z * sC : nullptr;
    #pragma unroll
    for (int mi = 0; mi < 2; ++mi) {
        int row = m0 + wm + mi * 16 + g;
        #pragma unroll
        for (int ni = 0; ni < 8; ++ni) {
            int col = n0 + wn + ni * 8 + t2;
            float2 v0 = make_float2(acc[mi][ni][0], acc[mi][ni][1]);
            float2 v1 = make_float2(acc[mi][ni][2], acc[mi][ni][3]);
            if (EPI == 0) {
                float b0 = Rb[row], b1 = Rb[row + 8];
                v0.x += b0; v0.y += b0;
                v1.x += b1; v1.y += b1;
            } else if (EPI == 2) {
                float2 q0 = *reinterpret_cast<const float2*>(&Rb[(size_t)row * ldc + col]);
                float2 q1 = *reinterpret_cast<const float2*>(&Rb[(size_t)(row + 8) * ldc + col]);
                v0.x = gm * v0.x + q0.x; v0.y = gm * v0.y + q0.y;
                v1.x = gm * v1.x + q1.x; v1.y = gm * v1.y + q1.y;
            }
            *reinterpret_cast<float2*>(&Cb[(size_t)row * ldc + col]) = v0;
            *reinterpret_cast<float2*>(&Cb[(size_t)(row + 8) * ldc + col]) = v1;
            if (EPI == 0) {
                __half hx, lx, hy, ly;
                split1(v0.x, hx, lx); split1(v0.y, hy, ly);
                *reinterpret_cast<__half2*>(&oh[(size_t)row * ldc + col]) = __halves2half2(hx, hy);
                *reinterpret_cast<__half2*>(&ol[(size_t)row * ldc + col]) = __halves2half2(lx, ly);
                split1(v1.x, hx, lx); split1(v1.y, hy, ly);
                *reinterpret_cast<__half2*>(&oh[(size_t)(row + 8) * ldc + col]) = __halves2half2(hx, hy);
                *reinterpret_cast<__half2*>(&ol[(size_t)(row + 8) * ldc + col]) = __halves2half2(lx, ly);
            }
        }
    }
}

// ---------------------------------------------------------------------------
// Softmax: reduce split-K partials, scale, softmax, emit att hi/lo fp16
// ---------------------------------------------------------------------------
__global__ __launch_bounds__(128) void softmax_rows()
{
    const int row = blockIdx.x;              // b*C1 + m
    const int b   = row / C1;
    const int m   = row % C1;
    const int tid = threadIdx.x;
    const size_t p0 = ((size_t)b * KSPLIT_E) * C1 * CIN + (size_t)m * CIN + tid * 4;
    const size_t pk = (size_t)C1 * CIN;

    float4 a0 = *reinterpret_cast<const float4*>(&g_ep[p0]);
    float4 a1 = *reinterpret_cast<const float4*>(&g_ep[p0 + pk]);
    float v[4];
    v[0] = (a0.x + a1.x) * INV_SQRT_HW;
    v[1] = (a0.y + a1.y) * INV_SQRT_HW;
    v[2] = (a0.z + a1.z) * INV_SQRT_HW;
    v[3] = (a0.w + a1.w) * INV_SQRT_HW;

    float mx = fmaxf(fmaxf(v[0], v[1]), fmaxf(v[2], v[3]));
    #pragma unroll
    for (int off = 16; off > 0; off >>= 1)
        mx = fmaxf(mx, __shfl_xor_sync(0xffffffffu, mx, off));
    __shared__ float red[4];
    const int lane = tid & 31, wid = tid >> 5;
    if (lane == 0) red[wid] = mx;
    __syncthreads();
    mx = fmaxf(fmaxf(red[0], red[1]), fmaxf(red[2], red[3]));
    __syncthreads();

    float e[4], s = 0.f;
    #pragma unroll
    for (int i = 0; i < 4; ++i) { e[i] = expf(v[i] - mx); s += e[i]; }
    #pragma unroll
    for (int off = 16; off > 0; off >>= 1)
        s += __shfl_xor_sync(0xffffffffu, s, off);
    if (lane == 0) red[wid] = s;
    __syncthreads();
    s = red[0] + red[1] + red[2] + red[3];
    const float inv = 1.0f / s;

    const size_t ob = (size_t)row * CIN + tid * 4;
    __half h[4], l[4];
    #pragma unroll
    for (int i = 0; i < 4; ++i) split1(e[i] * inv, h[i], l[i]);
    *reinterpret_cast<__half2*>(&g_a_hi[ob])     = __halves2half2(h[0], h[1]);
    *reinterpret_cast<__half2*>(&g_a_hi[ob + 2]) = __halves2half2(h[2], h[3]);
    *reinterpret_cast<__half2*>(&g_a_lo[ob])     = __halves2half2(l[0], l[1]);
    *reinterpret_cast<__half2*>(&g_a_lo[ob + 2]) = __halves2half2(l[2], l[3]);
}

// ---------------------------------------------------------------------------
extern "C" void kernel_launch(void* const* d_in, const int* in_sizes, int n_in,
                              void* d_out, int out_size)
{
    const float* x     = (const float*)d_in[0];  // (16,512,64,64)
    const float* convw = (const float*)d_in[1];  // (256,512,1,1)
    const float* convb = (const float*)d_in[2];  // (256,)
    const float* gamma = (const float*)d_in[3];  // (1,)
    float* out = (float*)d_out;                  // (16,256,64,64)

    cudaFuncSetAttribute(gemm_mma<0>, cudaFuncAttributeMaxDynamicSharedMemorySize, DYN_SMEM);
    cudaFuncSetAttribute(gemm_mma<1>, cudaFuncAttributeMaxDynamicSharedMemorySize, DYN_SMEM);
    cudaFuncSetAttribute(gemm_mma<2>, cudaFuncAttributeMaxDynamicSharedMemorySize, DYN_SMEM);

    float*  qptr = nullptr; cudaGetSymbolAddress((void**)&qptr,  g_q);
    __half* qh   = nullptr; cudaGetSymbolAddress((void**)&qh,    g_q_hi);
    __half* ql   = nullptr; cudaGetSymbolAddress((void**)&ql,    g_q_lo);
    __half* xh   = nullptr; cudaGetSymbolAddress((void**)&xh,    g_x_hi);
    __half* xth  = nullptr; cudaGetSymbolAddress((void**)&xth,   g_xT_hi);
    __half* wh   = nullptr; cudaGetSymbolAddress((void**)&wh,    g_w_hi);
    __half* wl   = nullptr; cudaGetSymbolAddress((void**)&wl,    g_w_lo);
    float*  eptr = nullptr; cudaGetSymbolAddress((void**)&eptr,  g_ep);
    __half* ah   = nullptr; cudaGetSymbolAddress((void**)&ah,    g_a_hi);
    __half* al   = nullptr; cudaGetSymbolAddress((void**)&al,    g_a_lo);

    prep_x<<<dim3(HW / 32, CIN / 32, BATCH), dim3(32, 8)>>>(x);
    prep_w<<<(C1 * CIN + 255) / 256, 256>>>(convw);

    // proj: q = W x + b   (M=C1, N=HW, K=CIN); emits q fp32 + q hi/lo fp16
    gemm_mma<0><<<dim3(HW / BN, C1 / BM, BATCH), NTH, DYN_SMEM>>>(
        wh, wl, 0, CIN, xth, (size_t)HW * CIN, CIN,
        qptr, (size_t)C1 * HW, HW, CIN, 1, convb, 0, nullptr, qh, ql);

    // energy partials: e = q x^T  (M=C1, N=CIN, K=HW split 2)
    gemm_mma<1><<<dim3(CIN / BN, C1 / BM, BATCH * KSPLIT_E), NTH, DYN_SMEM>>>(
        qh, ql, (size_t)C1 * HW, HW, xh, (size_t)CIN * HW, HW,
        eptr, (size_t)C1 * CIN, CIN, HW / KSPLIT_E, KSPLIT_E,
        nullptr, 0, nullptr, nullptr, nullptr);

    softmax_rows<<<BATCH * C1, 128>>>();

    // out: gamma*(att x) + q  (M=C1, N=HW, K=CIN)
    gemm_mma<2><<<dim3(HW / BN, C1 / BM, BATCH), NTH, DYN_SMEM>>>(
        ah, al, (size_t)C1 * CIN, CIN, xth, (size_t)HW * CIN, CIN,
        out, (size_t)C1 * HW, HW, CIN, 1,
        qptr, (size_t)C1 * HW, gamma, nullptr, nullptr);
}

// round 6
// speedup vs baseline: 3.1942x; 1.0337x over previous
#include <cuda_runtime.h>
#include <cuda_fp16.h>
#include <stdint.h>
#include <math.h>

// Problem constants
#define BATCH 16
#define CIN   512
#define C1    256
#define HW    4096
#define INV_SQRT_HW (1.0f/64.0f)

// GEMM tiling
#define BM 128
#define BN 128
#define BK 32
#define NTH 256
#define SROW 40                 // padded row stride in halves (80 B)

// SMEM stage layout (bytes)
#define TILE_B (BM * SROW * 2)  // 10240
#define T_AHI 0
#define T_ALO TILE_B
#define T_BHI (2 * TILE_B)
#define STAGE_B (3 * TILE_B)    // 30720
#define DYN_SMEM (2 * STAGE_B)  // 61440

#define KSPLIT_E 2

// Scratch (allocation-free rule: __device__ globals)
__device__ __align__(16) float  g_q   [(size_t)BATCH * C1 * HW];
__device__ __align__(16) __half g_q_hi[(size_t)BATCH * C1 * HW];
__device__ __align__(16) __half g_q_lo[(size_t)BATCH * C1 * HW];
__device__ __align__(16) __half g_x_hi[(size_t)BATCH * CIN * HW];
__device__ __align__(16) __half g_xT_hi[(size_t)BATCH * HW * CIN];
__device__ __align__(16) __half g_w_hi[(size_t)C1 * CIN];
__device__ __align__(16) __half g_w_lo[(size_t)C1 * CIN];
__device__ __align__(16) float  g_ep  [(size_t)BATCH * KSPLIT_E * C1 * CIN];
__device__ __align__(16) __half g_a_hi[(size_t)BATCH * C1 * CIN];
__device__ __align__(16) __half g_a_lo[(size_t)BATCH * C1 * CIN];

// ---------------- helpers ----------------
__device__ __forceinline__ uint32_t smem_u32(const void* p) {
    uint32_t a;
    asm("{ .reg .u64 t; cvta.to.shared.u64 t, %1; cvt.u32.u64 %0, t; }" : "=r"(a) : "l"(p));
    return a;
}
__device__ __forceinline__ void cpasync16(uint32_t dst, const void* src) {
    asm volatile("cp.async.cg.shared.global [%0], [%1], 16;" :: "r"(dst), "l"(src) : "memory");
}
#define CP_COMMIT() asm volatile("cp.async.commit_group;" ::: "memory")
#define CP_WAIT(n)  asm volatile("cp.async.wait_group %0;" :: "n"(n) : "memory")

__device__ __forceinline__ void mma16816(float* d, const uint32_t* a, uint32_t b0, uint32_t b1) {
    asm volatile(
        "mma.sync.aligned.m16n8k16.row.col.f32.f16.f16.f32 "
        "{%0,%1,%2,%3}, {%4,%5,%6,%7}, {%8,%9}, {%0,%1,%2,%3};"
        : "+f"(d[0]), "+f"(d[1]), "+f"(d[2]), "+f"(d[3])
        : "r"(a[0]), "r"(a[1]), "r"(a[2]), "r"(a[3]), "r"(b0), "r"(b1));
}
__device__ __forceinline__ void ldsm4(uint32_t* r, uint32_t addr) {
    asm volatile("ldmatrix.sync.aligned.m8n8.x4.shared.b16 {%0,%1,%2,%3}, [%4];"
        : "=r"(r[0]), "=r"(r[1]), "=r"(r[2]), "=r"(r[3]) : "r"(addr));
}
__device__ __forceinline__ void split1(float v, __half& hi, __half& lo) {
    hi = __float2half_rn(v);
    lo = __float2half_rn(v - __half2float(hi));
}

// ---------------------------------------------------------------------------
// prep_x: x fp32 -> x_hi (same layout) + xT_hi (transposed), fp16
// ---------------------------------------------------------------------------
__global__ __launch_bounds__(256) void prep_x(const float* __restrict__ x)
{
    __shared__ float t[32][33];
    const int b = blockIdx.z;
    const int n0 = blockIdx.x * 32, c0 = blockIdx.y * 32;
    const int tx = threadIdx.x, ty = threadIdx.y;   // (32, 8)
    const float* xs = x + (size_t)b * CIN * HW;
    __half* xh  = g_x_hi  + (size_t)b * CIN * HW;
    __half* xth = g_xT_hi + (size_t)b * HW * CIN;
    #pragma unroll
    for (int i = 0; i < 4; ++i) {
        float v = xs[(size_t)(c0 + ty + i * 8) * HW + n0 + tx];
        t[ty + i * 8][tx] = v;
        xh[(size_t)(c0 + ty + i * 8) * HW + n0 + tx] = __float2half_rn(v);
    }
    __syncthreads();
    #pragma unroll
    for (int i = 0; i < 4; ++i)
        xth[(size_t)(n0 + ty + i * 8) * CIN + c0 + tx] = __float2half_rn(t[tx][ty + i * 8]);
}

// prep_w: W fp32 -> hi/lo fp16
__global__ __launch_bounds__(256) void prep_w(const float* __restrict__ w)
{
    int f = blockIdx.x * 256 + threadIdx.x;
    if (f < C1 * CIN) {
        __half h, l; split1(w[f], h, l);
        g_w_hi[f] = h; g_w_lo[f] = l;
    }
}

// ---------------------------------------------------------------------------
// NT GEMM (fp16 2-pass, cp.async double-buffered, ldmatrix frags):
//   D[m][n] = sum_k (Ahi+Alo)[m][k] * Bhi[n][k]
// EPI 0: +bias, also emit hi/lo fp16   EPI 1: raw   EPI 2: gamma*acc + res
// grid: (N/BN, M/BM, BATCH*zdiv)
// ---------------------------------------------------------------------------
template<int EPI>
__global__ __launch_bounds__(NTH, 2) void gemm_mma(
    const __half* __restrict__ Ahi, const __half* __restrict__ Alo, size_t sA, int lda,
    const __half* __restrict__ Bhi, size_t sB, int ldb,
    float* __restrict__ C, size_t sC, int ldc,
    int K, int zdiv,
    const float* __restrict__ aux, size_t sAux,
    const float* __restrict__ gamma,
    __half* __restrict__ outHi, __half* __restrict__ outLo)
{
    extern __shared__ char dyn[];
    const uint32_t sbase = smem_u32(dyn);

    const int tid  = threadIdx.x;
    const int z    = blockIdx.z;
    const int b    = z / zdiv;
    const int kbase = (z % zdiv) * K;
    const int m0 = blockIdx.y * BM;
    const int n0 = blockIdx.x * BN;

    const __half* Ah = Ahi + (size_t)b * sA + kbase;
    const __half* Al = Alo + (size_t)b * sA + kbase;
    const __half* Bh = Bhi + (size_t)b * sB + kbase;
    float*        Cb = C   + (size_t)z * sC;

    const int wid = tid >> 5, lane = tid & 31;
    const int wm = (wid & 3) * 32;
    const int wn = (wid >> 2) * 64;
    const int g  = lane >> 2;
    const int t2 = (lane & 3) * 2;

    // ldmatrix per-lane row offsets (in halves)
    const int l7  = lane & 7;
    const int t8  = (lane >> 3) & 1;   // tile bit 0
    const int t16 = lane >> 4;         // tile bit 1
    int aoff[2], boff[4];
    #pragma unroll
    for (int mi = 0; mi < 2; ++mi)
        aoff[mi] = (wm + mi * 16 + t8 * 8 + l7) * SROW + t16 * 8;
    #pragma unroll
    for (int nb = 0; nb < 4; ++nb)
        boff[nb] = (wn + nb * 16 + t16 * 8 + l7) * SROW + t8 * 8;

    // per-thread fill coords: 2 chunks of 16B per array per stage
    const int fr0 = tid >> 2, fc0 = tid & 3;
    const int fr1 = (tid + NTH) >> 2, fc1 = (tid + NTH) & 3;

    float acc[2][8][4];
    #pragma unroll
    for (int mi = 0; mi < 2; ++mi)
        #pragma unroll
        for (int ni = 0; ni < 8; ++ni)
            #pragma unroll
            for (int r = 0; r < 4; ++r) acc[mi][ni][r] = 0.f;

    const int nst = K / BK;

#define ISSUE(s) do {                                                              \
        const uint32_t sb_ = sbase + ((s) & 1) * STAGE_B;                          \
        const int k0_ = (s) * BK;                                                  \
        cpasync16(sb_ + T_AHI + fr0 * 80 + fc0 * 16, Ah + (size_t)(m0 + fr0) * lda + k0_ + fc0 * 8); \
        cpasync16(sb_ + T_AHI + fr1 * 80 + fc1 * 16, Ah + (size_t)(m0 + fr1) * lda + k0_ + fc1 * 8); \
        cpasync16(sb_ + T_ALO + fr0 * 80 + fc0 * 16, Al + (size_t)(m0 + fr0) * lda + k0_ + fc0 * 8); \
        cpasync16(sb_ + T_ALO + fr1 * 80 + fc1 * 16, Al + (size_t)(m0 + fr1) * lda + k0_ + fc1 * 8); \
        cpasync16(sb_ + T_BHI + fr0 * 80 + fc0 * 16, Bh + (size_t)(n0 + fr0) * ldb + k0_ + fc0 * 8); \
        cpasync16(sb_ + T_BHI + fr1 * 80 + fc1 * 16, Bh + (size_t)(n0 + fr1) * ldb + k0_ + fc1 * 8); \
        CP_COMMIT();                                                               \
    } while (0)

    ISSUE(0);
    for (int s = 0; s < nst; ++s) {
        if (s + 1 < nst) { ISSUE(s + 1); CP_WAIT(1); }
        else             { CP_WAIT(0); }
        __syncthreads();

        const uint32_t stg = sbase + (s & 1) * STAGE_B;
        const uint32_t aHiB = stg + T_AHI;
        const uint32_t aLoB = stg + T_ALO;
        const uint32_t bHiB = stg + T_BHI;

        #pragma unroll
        for (int kk = 0; kk < BK; kk += 16) {
            uint32_t ah[2][4], al[2][4];
            ldsm4(ah[0], aHiB + 2 * (aoff[0] + kk));
            ldsm4(ah[1], aHiB + 2 * (aoff[1] + kk));
            ldsm4(al[0], aLoB + 2 * (aoff[0] + kk));
            ldsm4(al[1], aLoB + 2 * (aoff[1] + kk));
            #pragma unroll
            for (int nb = 0; nb < 4; ++nb) {
                uint32_t bb[4];
                ldsm4(bb, bHiB + 2 * (boff[nb] + kk));
                #pragma unroll
                for (int mi = 0; mi < 2; ++mi) {
                    mma16816(acc[mi][nb * 2 + 0], ah[mi], bb[0], bb[1]);
                    mma16816(acc[mi][nb * 2 + 0], al[mi], bb[0], bb[1]);
                    mma16816(acc[mi][nb * 2 + 1], ah[mi], bb[2], bb[3]);
                    mma16816(acc[mi][nb * 2 + 1], al[mi], bb[2], bb[3]);
                }
            }
        }
        __syncthreads();
    }
#undef ISSUE

    // ---- epilogue ----
    const float gm = (EPI == 2) ? __ldg(gamma) : 0.f;
    const float* Rb = (EPI == 2) ? aux + (size_t)b * sAux : aux;
    __half* oh = (EPI == 0) ? outHi + (size_t)z * sC : nullptr;
    __half* ol = (EPI == 0) ? outLo + (size_t)z * sC : nullptr;
    #pragma unroll
    for (int mi = 0; mi < 2; ++mi) {
        int row = m0 + wm + mi * 16 + g;
        #pragma unroll
        for (int ni = 0; ni < 8; ++ni) {
            int col = n0 + wn + ni * 8 + t2;
            float2 v0 = make_float2(acc[mi][ni][0], acc[mi][ni][1]);
            float2 v1 = make_float2(acc[mi][ni][2], acc[mi][ni][3]);
            if (EPI == 0) {
                float b0 = Rb[row], b1 = Rb[row + 8];
                v0.x += b0; v0.y += b0;
                v1.x += b1; v1.y += b1;
            } else if (EPI == 2) {
                float2 q0 = *reinterpret_cast<const float2*>(&Rb[(size_t)row * ldc + col]);
                float2 q1 = *reinterpret_cast<const float2*>(&Rb[(size_t)(row + 8) * ldc + col]);
                v0.x = gm * v0.x + q0.x; v0.y = gm * v0.y + q0.y;
                v1.x = gm * v1.x + q1.x; v1.y = gm * v1.y + q1.y;
            }
            *reinterpret_cast<float2*>(&Cb[(size_t)row * ldc + col]) = v0;
            *reinterpret_cast<float2*>(&Cb[(size_t)(row + 8) * ldc + col]) = v1;
            if (EPI == 0) {
                __half hx, lx, hy, ly;
                split1(v0.x, hx, lx); split1(v0.y, hy, ly);
                *reinterpret_cast<__half2*>(&oh[(size_t)row * ldc + col]) = __halves2half2(hx, hy);
                *reinterpret_cast<__half2*>(&ol[(size_t)row * ldc + col]) = __halves2half2(lx, ly);
                split1(v1.x, hx, lx); split1(v1.y, hy, ly);
                *reinterpret_cast<__half2*>(&oh[(size_t)(row + 8) * ldc + col]) = __halves2half2(hx, hy);
                *reinterpret_cast<__half2*>(&ol[(size_t)(row + 8) * ldc + col]) = __halves2half2(lx, ly);
            }
        }
    }
}

// ---------------------------------------------------------------------------
// Softmax: reduce split-K partials, scale, softmax, emit att hi/lo fp16
// ---------------------------------------------------------------------------
__global__ __launch_bounds__(128) void softmax_rows()
{
    const int row = blockIdx.x;              // b*C1 + m
    const int b   = row / C1;
    const int m   = row % C1;
    const int tid = threadIdx.x;
    const size_t p0 = ((size_t)b * KSPLIT_E) * C1 * CIN + (size_t)m * CIN + tid * 4;
    const size_t pk = (size_t)C1 * CIN;

    float4 a0 = *reinterpret_cast<const float4*>(&g_ep[p0]);
    float4 a1 = *reinterpret_cast<const float4*>(&g_ep[p0 + pk]);
    float v[4];
    v[0] = (a0.x + a1.x) * INV_SQRT_HW;
    v[1] = (a0.y + a1.y) * INV_SQRT_HW;
    v[2] = (a0.z + a1.z) * INV_SQRT_HW;
    v[3] = (a0.w + a1.w) * INV_SQRT_HW;

    float mx = fmaxf(fmaxf(v[0], v[1]), fmaxf(v[2], v[3]));
    #pragma unroll
    for (int off = 16; off > 0; off >>= 1)
        mx = fmaxf(mx, __shfl_xor_sync(0xffffffffu, mx, off));
    __shared__ float red[4];
    const int lane = tid & 31, wid = tid >> 5;
    if (lane == 0) red[wid] = mx;
    __syncthreads();
    mx = fmaxf(fmaxf(red[0], red[1]), fmaxf(red[2], red[3]));
    __syncthreads();

    float e[4], s = 0.f;
    #pragma unroll
    for (int i = 0; i < 4; ++i) { e[i] = expf(v[i] - mx); s += e[i]; }
    #pragma unroll
    for (int off = 16; off > 0; off >>= 1)
        s += __shfl_xor_sync(0xffffffffu, s, off);
    if (lane == 0) red[wid] = s;
    __syncthreads();
    s = red[0] + red[1] + red[2] + red[3];
    const float inv = 1.0f / s;

    const size_t ob = (size_t)row * CIN + tid * 4;
    __half h[4], l[4];
    #pragma unroll
    for (int i = 0; i < 4; ++i) split1(e[i] * inv, h[i], l[i]);
    *reinterpret_cast<__half2*>(&g_a_hi[ob])     = __halves2half2(h[0], h[1]);
    *reinterpret_cast<__half2*>(&g_a_hi[ob + 2]) = __halves2half2(h[2], h[3]);
    *reinterpret_cast<__half2*>(&g_a_lo[ob])     = __halves2half2(l[0], l[1]);
    *reinterpret_cast<__half2*>(&g_a_lo[ob + 2]) = __halves2half2(l[2], l[3]);
}

// ---------------------------------------------------------------------------
extern "C" void kernel_launch(void* const* d_in, const int* in_sizes, int n_in,
                              void* d_out, int out_size)
{
    const float* x     = (const float*)d_in[0];  // (16,512,64,64)
    const float* convw = (const float*)d_in[1];  // (256,512,1,1)
    const float* convb = (const float*)d_in[2];  // (256,)
    const float* gamma = (const float*)d_in[3];  // (1,)
    float* out = (float*)d_out;                  // (16,256,64,64)

    cudaFuncSetAttribute(gemm_mma<0>, cudaFuncAttributeMaxDynamicSharedMemorySize, DYN_SMEM);
    cudaFuncSetAttribute(gemm_mma<1>, cudaFuncAttributeMaxDynamicSharedMemorySize, DYN_SMEM);
    cudaFuncSetAttribute(gemm_mma<2>, cudaFuncAttributeMaxDynamicSharedMemorySize, DYN_SMEM);

    float*  qptr = nullptr; cudaGetSymbolAddress((void**)&qptr,  g_q);
    __half* qh   = nullptr; cudaGetSymbolAddress((void**)&qh,    g_q_hi);
    __half* ql   = nullptr; cudaGetSymbolAddress((void**)&ql,    g_q_lo);
    __half* xh   = nullptr; cudaGetSymbolAddress((void**)&xh,    g_x_hi);
    __half* xth  = nullptr; cudaGetSymbolAddress((void**)&xth,   g_xT_hi);
    __half* wh   = nullptr; cudaGetSymbolAddress((void**)&wh,    g_w_hi);
    __half* wl   = nullptr; cudaGetSymbolAddress((void**)&wl,    g_w_lo);
    float*  eptr = nullptr; cudaGetSymbolAddress((void**)&eptr,  g_ep);
    __half* ah   = nullptr; cudaGetSymbolAddress((void**)&ah,    g_a_hi);
    __half* al   = nullptr; cudaGetSymbolAddress((void**)&al,    g_a_lo);

    prep_x<<<dim3(HW / 32, CIN / 32, BATCH), dim3(32, 8)>>>(x);
    prep_w<<<(C1 * CIN + 255) / 256, 256>>>(convw);

    // proj: q = W x + b   (M=C1, N=HW, K=CIN); emits q fp32 + q hi/lo fp16
    gemm_mma<0><<<dim3(HW / BN, C1 / BM, BATCH), NTH, DYN_SMEM>>>(
        wh, wl, 0, CIN, xth, (size_t)HW * CIN, CIN,
        qptr, (size_t)C1 * HW, HW, CIN, 1, convb, 0, nullptr, qh, ql);

    // energy partials: e = q x^T  (M=C1, N=CIN, K=HW split 2)
    gemm_mma<1><<<dim3(CIN / BN, C1 / BM, BATCH * KSPLIT_E), NTH, DYN_SMEM>>>(
        qh, ql, (size_t)C1 * HW, HW, xh, (size_t)CIN * HW, HW,
        eptr, (size_t)C1 * CIN, CIN, HW / KSPLIT_E, KSPLIT_E,
        nullptr, 0, nullptr, nullptr, nullptr);

    softmax_rows<<<BATCH * C1, 128>>>();

    // out: gamma*(att x) + q  (M=C1, N=HW, K=CIN)
    gemm_mma<2><<<dim3(HW / BN, C1 / BM, BATCH), NTH, DYN_SMEM>>>(
        ah, al, (size_t)C1 * CIN, CIN, xth, (size_t)HW * CIN, CIN,
        out, (size_t)C1 * HW, HW, CIN, 1,
        qptr, (size_t)C1 * HW, gamma, nullptr, nullptr);
}

// round 8
// speedup vs baseline: 3.3219x; 1.0400x over previous
#include <cuda_runtime.h>
#include <cuda_fp16.h>
#include <stdint.h>
#include <math.h>

// Problem constants
#define BATCH 16
#define CIN   512
#define C1    256
#define HW    4096
#define INV_SQRT_HW (1.0f/64.0f)

// GEMM tiling
#define BM 128
#define BN 128
#define BK 32
#define NTH 256
#define SROW 40                 // padded row stride in halves (80 B)
#define NSTAGE 3

// SMEM stage layout (bytes)
#define TILE_B (BM * SROW * 2)  // 10240
#define T_AHI 0
#define T_ALO TILE_B
#define T_BHI (2 * TILE_B)
#define STAGE_B (3 * TILE_B)    // 30720
#define DYN_SMEM (NSTAGE * STAGE_B)  // 92160

#define KSPLIT_E 2

// Scratch (allocation-free rule: __device__ globals)
__device__ __align__(16) float  g_q   [(size_t)BATCH * C1 * HW];
__device__ __align__(16) __half g_q_hi[(size_t)BATCH * C1 * HW];
__device__ __align__(16) __half g_q_lo[(size_t)BATCH * C1 * HW];
__device__ __align__(16) __half g_x_hi[(size_t)BATCH * CIN * HW];
__device__ __align__(16) __half g_xT_hi[(size_t)BATCH * HW * CIN];
__device__ __align__(16) __half g_w_hi[(size_t)C1 * CIN];
__device__ __align__(16) __half g_w_lo[(size_t)C1 * CIN];
__device__ __align__(16) float  g_ep  [(size_t)BATCH * KSPLIT_E * C1 * CIN];
__device__ __align__(16) __half g_a_hi[(size_t)BATCH * C1 * CIN];
__device__ __align__(16) __half g_a_lo[(size_t)BATCH * C1 * CIN];

// ---------------- helpers ----------------
__device__ __forceinline__ uint32_t smem_u32(const void* p) {
    uint32_t a;
    asm("{ .reg .u64 t; cvta.to.shared.u64 t, %1; cvt.u32.u64 %0, t; }" : "=r"(a) : "l"(p));
    return a;
}
__device__ __forceinline__ void cpasync16(uint32_t dst, const void* src) {
    asm volatile("cp.async.cg.shared.global [%0], [%1], 16;" :: "r"(dst), "l"(src) : "memory");
}
#define CP_COMMIT() asm volatile("cp.async.commit_group;" ::: "memory")
#define CP_WAIT(n)  asm volatile("cp.async.wait_group %0;" :: "n"(n) : "memory")

__device__ __forceinline__ void mma16816(float* d, const uint32_t* a, uint32_t b0, uint32_t b1) {
    asm volatile(
        "mma.sync.aligned.m16n8k16.row.col.f32.f16.f16.f32 "
        "{%0,%1,%2,%3}, {%4,%5,%6,%7}, {%8,%9}, {%0,%1,%2,%3};"
        : "+f"(d[0]), "+f"(d[1]), "+f"(d[2]), "+f"(d[3])
        : "r"(a[0]), "r"(a[1]), "r"(a[2]), "r"(a[3]), "r"(b0), "r"(b1));
}
__device__ __forceinline__ void ldsm4(uint32_t* r, uint32_t addr) {
    asm volatile("ldmatrix.sync.aligned.m8n8.x4.shared.b16 {%0,%1,%2,%3}, [%4];"
        : "=r"(r[0]), "=r"(r[1]), "=r"(r[2]), "=r"(r[3]) : "r"(addr));
}
__device__ __forceinline__ void split1(float v, __half& hi, __half& lo) {
    hi = __float2half_rn(v);
    lo = __float2half_rn(v - __half2float(hi));
}

// ---------------------------------------------------------------------------
// prep_x: x fp32 -> x_hi (same layout) + xT_hi (transposed), fp16
// ---------------------------------------------------------------------------
__global__ __launch_bounds__(256) void prep_x(const float* __restrict__ x)
{
    __shared__ float t[32][33];
    const int b = blockIdx.z;
    const int n0 = blockIdx.x * 32, c0 = blockIdx.y * 32;
    const int tx = threadIdx.x, ty = threadIdx.y;   // (32, 8)
    const float* xs = x + (size_t)b * CIN * HW;
    __half* xh  = g_x_hi  + (size_t)b * CIN * HW;
    __half* xth = g_xT_hi + (size_t)b * HW * CIN;
    #pragma unroll
    for (int i = 0; i < 4; ++i) {
        float v = xs[(size_t)(c0 + ty + i * 8) * HW + n0 + tx];
        t[ty + i * 8][tx] = v;
        xh[(size_t)(c0 + ty + i * 8) * HW + n0 + tx] = __float2half_rn(v);
    }
    __syncthreads();
    #pragma unroll
    for (int i = 0; i < 4; ++i)
        xth[(size_t)(n0 + ty + i * 8) * CIN + c0 + tx] = __float2half_rn(t[tx][ty + i * 8]);
}

// prep_w: W fp32 -> hi/lo fp16
__global__ __launch_bounds__(256) void prep_w(const float* __restrict__ w)
{
    int f = blockIdx.x * 256 + threadIdx.x;
    if (f < C1 * CIN) {
        __half h, l; split1(w[f], h, l);
        g_w_hi[f] = h; g_w_lo[f] = l;
    }
}

// ---------------------------------------------------------------------------
// NT GEMM (fp16 2-pass, 3-stage cp.async pipeline, ldmatrix frags):
//   D[m][n] = sum_k (Ahi+Alo)[m][k] * Bhi[n][k]
// EPI 0: +bias, also emit hi/lo fp16   EPI 1: raw   EPI 2: gamma*acc + res
// grid: (N/BN, M/BM, BATCH*zdiv)
// ---------------------------------------------------------------------------
template<int EPI>
__global__ __launch_bounds__(NTH, 2) void gemm_mma(
    const __half* __restrict__ Ahi, const __half* __restrict__ Alo, size_t sA, int lda,
    const __half* __restrict__ Bhi, size_t sB, int ldb,
    float* __restrict__ C, size_t sC, int ldc,
    int K, int zdiv,
    const float* __restrict__ aux, size_t sAux,
    const float* __restrict__ gamma,
    __half* __restrict__ outHi, __half* __restrict__ outLo)
{
    extern __shared__ char dyn[];
    const uint32_t sbase = smem_u32(dyn);

    const int tid  = threadIdx.x;
    const int z    = blockIdx.z;
    const int b    = z / zdiv;
    const int kbase = (z % zdiv) * K;
    const int m0 = blockIdx.y * BM;
    const int n0 = blockIdx.x * BN;

    const __half* Ah = Ahi + (size_t)b * sA + kbase;
    const __half* Al = Alo + (size_t)b * sA + kbase;
    const __half* Bh = Bhi + (size_t)b * sB + kbase;
    float*        Cb = C   + (size_t)z * sC;

    const int wid = tid >> 5, lane = tid & 31;
    const int wm = (wid & 3) * 32;
    const int wn = (wid >> 2) * 64;
    const int g  = lane >> 2;
    const int t2 = (lane & 3) * 2;

    // ldmatrix per-lane row offsets (in halves)
    const int l7  = lane & 7;
    const int t8  = (lane >> 3) & 1;
    const int t16 = lane >> 4;
    int aoff[2], boff[4];
    #pragma unroll
    for (int mi = 0; mi < 2; ++mi)
        aoff[mi] = (wm + mi * 16 + t8 * 8 + l7) * SROW + t16 * 8;
    #pragma unroll
    for (int nb = 0; nb < 4; ++nb)
        boff[nb] = (wn + nb * 16 + t16 * 8 + l7) * SROW + t8 * 8;

    // per-thread fill coords: 2 chunks of 16B per array per stage
    const int fr0 = tid >> 2, fc0 = tid & 3;
    const int fr1 = (tid + NTH) >> 2, fc1 = (tid + NTH) & 3;

    float acc[2][8][4];
    #pragma unroll
    for (int mi = 0; mi < 2; ++mi)
        #pragma unroll
        for (int ni = 0; ni < 8; ++ni)
            #pragma unroll
            for (int r = 0; r < 4; ++r) acc[mi][ni][r] = 0.f;

    const int nst = K / BK;

#define ISSUE(s) do {                                                              \
        const uint32_t sb_ = sbase + ((s) % NSTAGE) * STAGE_B;                     \
        const int k0_ = (s) * BK;                                                  \
        cpasync16(sb_ + T_AHI + fr0 * 80 + fc0 * 16, Ah + (size_t)(m0 + fr0) * lda + k0_ + fc0 * 8); \
        cpasync16(sb_ + T_AHI + fr1 * 80 + fc1 * 16, Ah + (size_t)(m0 + fr1) * lda + k0_ + fc1 * 8); \
        cpasync16(sb_ + T_ALO + fr0 * 80 + fc0 * 16, Al + (size_t)(m0 + fr0) * lda + k0_ + fc0 * 8); \
        cpasync16(sb_ + T_ALO + fr1 * 80 + fc1 * 16, Al + (size_t)(m0 + fr1) * lda + k0_ + fc1 * 8); \
        cpasync16(sb_ + T_BHI + fr0 * 80 + fc0 * 16, Bh + (size_t)(n0 + fr0) * ldb + k0_ + fc0 * 8); \
        cpasync16(sb_ + T_BHI + fr1 * 80 + fc1 * 16, Bh + (size_t)(n0 + fr1) * ldb + k0_ + fc1 * 8); \
        CP_COMMIT();                                                               \
    } while (0)

    // prologue: 2 stages in flight
    ISSUE(0);
    ISSUE(1);
    for (int s = 0; s < nst; ++s) {
        if (s + 1 < nst) CP_WAIT(1); else CP_WAIT(0);
        __syncthreads();                 // stage s ready; all warps done reading stage s-1
        if (s + 2 < nst) ISSUE(s + 2);   // refill buffer (s+2)%3 (= stage s-1's buffer)

        const uint32_t stg = sbase + (s % NSTAGE) * STAGE_B;
        const uint32_t aHiB = stg + T_AHI;
        const uint32_t aLoB = stg + T_ALO;
        const uint32_t bHiB = stg + T_BHI;

        #pragma unroll
        for (int kk = 0; kk < BK; kk += 16) {
            uint32_t ah[2][4], al[2][4];
            ldsm4(ah[0], aHiB + 2 * (aoff[0] + kk));
            ldsm4(ah[1], aHiB + 2 * (aoff[1] + kk));
            ldsm4(al[0], aLoB + 2 * (aoff[0] + kk));
            ldsm4(al[1], aLoB + 2 * (aoff[1] + kk));
            #pragma unroll
            for (int nb = 0; nb < 4; ++nb) {
                uint32_t bb[4];
                ldsm4(bb, bHiB + 2 * (boff[nb] + kk));
                #pragma unroll
                for (int mi = 0; mi < 2; ++mi) {
                    mma16816(acc[mi][nb * 2 + 0], ah[mi], bb[0], bb[1]);
                    mma16816(acc[mi][nb * 2 + 0], al[mi], bb[0], bb[1]);
                    mma16816(acc[mi][nb * 2 + 1], ah[mi], bb[2], bb[3]);
                    mma16816(acc[mi][nb * 2 + 1], al[mi], bb[2], bb[3]);
                }
            }
        }
    }
#undef ISSUE

    // ---- epilogue ----
    const float gm = (EPI == 2) ? __ldg(gamma) : 0.f;
    const float* Rb = (EPI == 2) ? aux + (size_t)b * sAux : aux;
    __half* oh = (EPI == 0) ? outHi + (size_t)z * sC : nullptr;
    __half* ol = (EPI == 0) ? outLo + (size_t)z * sC : nullptr;
    #pragma unroll
    for (int mi = 0; mi < 2; ++mi) {
        int row = m0 + wm + mi * 16 + g;
        #pragma unroll
        for (int ni = 0; ni < 8; ++ni) {
            int col = n0 + wn + ni * 8 + t2;
            float2 v0 = make_float2(acc[mi][ni][0], acc[mi][ni][1]);
            float2 v1 = make_float2(acc[mi][ni][2], acc[mi][ni][3]);
            if (EPI == 0) {
                float b0 = Rb[row], b1 = Rb[row + 8];
                v0.x += b0; v0.y += b0;
                v1.x += b1; v1.y += b1;
            } else if (EPI == 2) {
                float2 q0 = *reinterpret_cast<const float2*>(&Rb[(size_t)row * ldc + col]);
                float2 q1 = *reinterpret_cast<const float2*>(&Rb[(size_t)(row + 8) * ldc + col]);
                v0.x = gm * v0.x + q0.x; v0.y = gm * v0.y + q0.y;
                v1.x = gm * v1.x + q1.x; v1.y = gm * v1.y + q1.y;
            }
            *reinterpret_cast<float2*>(&Cb[(size_t)row * ldc + col]) = v0;
            *reinterpret_cast<float2*>(&Cb[(size_t)(row + 8) * ldc + col]) = v1;
            if (EPI == 0) {
                __half hx, lx, hy, ly;
                split1(v0.x, hx, lx); split1(v0.y, hy, ly);
                *reinterpret_cast<__half2*>(&oh[(size_t)row * ldc + col]) = __halves2half2(hx, hy);
                *reinterpret_cast<__half2*>(&ol[(size_t)row * ldc + col]) = __halves2half2(lx, ly);
                split1(v1.x, hx, lx); split1(v1.y, hy, ly);
                *reinterpret_cast<__half2*>(&oh[(size_t)(row + 8) * ldc + col]) = __halves2half2(hx, hy);
                *reinterpret_cast<__half2*>(&ol[(size_t)(row + 8) * ldc + col]) = __halves2half2(lx, ly);
            }
        }
    }
}

// ---------------------------------------------------------------------------
// Softmax: reduce split-K partials, scale, softmax, emit att hi/lo fp16
// ---------------------------------------------------------------------------
__global__ __launch_bounds__(128) void softmax_rows()
{
    const int row = blockIdx.x;              // b*C1 + m
    const int b   = row / C1;
    const int m   = row % C1;
    const int tid = threadIdx.x;
    const size_t p0 = ((size_t)b * KSPLIT_E) * C1 * CIN + (size_t)m * CIN + tid * 4;
    const size_t pk = (size_t)C1 * CIN;

    float4 a0 = *reinterpret_cast<const float4*>(&g_ep[p0]);
    float4 a1 = *reinterpret_cast<const float4*>(&g_ep[p0 + pk]);
    float v[4];
    v[0] = (a0.x + a1.x) * INV_SQRT_HW;
    v[1] = (a0.y + a1.y) * INV_SQRT_HW;
    v[2] = (a0.z + a1.z) * INV_SQRT_HW;
    v[3] = (a0.w + a1.w) * INV_SQRT_HW;

    float mx = fmaxf(fmaxf(v[0], v[1]), fmaxf(v[2], v[3]));
    #pragma unroll
    for (int off = 16; off > 0; off >>= 1)
        mx = fmaxf(mx, __shfl_xor_sync(0xffffffffu, mx, off));
    __shared__ float red[4];
    const int lane = tid & 31, wid = tid >> 5;
    if (lane == 0) red[wid] = mx;
    __syncthreads();
    mx = fmaxf(fmaxf(red[0], red[1]), fmaxf(red[2], red[3]));
    __syncthreads();

    float e[4], s = 0.f;
    #pragma unroll
    for (int i = 0; i < 4; ++i) { e[i] = expf(v[i] - mx); s += e[i]; }
    #pragma unroll
    for (int off = 16; off > 0; off >>= 1)
        s += __shfl_xor_sync(0xffffffffu, s, off);
    if (lane == 0) red[wid] = s;
    __syncthreads();
    s = red[0] + red[1] + red[2] + red[3];
    const float inv = 1.0f / s;

    const size_t ob = (size_t)row * CIN + tid * 4;
    __half h[4], l[4];
    #pragma unroll
    for (int i = 0; i < 4; ++i) split1(e[i] * inv, h[i], l[i]);
    *reinterpret_cast<__half2*>(&g_a_hi[ob])     = __halves2half2(h[0], h[1]);
    *reinterpret_cast<__half2*>(&g_a_hi[ob + 2]) = __halves2half2(h[2], h[3]);
    *reinterpret_cast<__half2*>(&g_a_lo[ob])     = __halves2half2(l[0], l[1]);
    *reinterpret_cast<__half2*>(&g_a_lo[ob + 2]) = __halves2half2(l[2], l[3]);
}

// ---------------------------------------------------------------------------
extern "C" void kernel_launch(void* const* d_in, const int* in_sizes, int n_in,
                              void* d_out, int out_size)
{
    const float* x     = (const float*)d_in[0];  // (16,512,64,64)
    const float* convw = (const float*)d_in[1];  // (256,512,1,1)
    const float* convb = (const float*)d_in[2];  // (256,)
    const float* gamma = (const float*)d_in[3];  // (1,)
    float* out = (float*)d_out;                  // (16,256,64,64)

    cudaFuncSetAttribute(gemm_mma<0>, cudaFuncAttributeMaxDynamicSharedMemorySize, DYN_SMEM);
    cudaFuncSetAttribute(gemm_mma<1>, cudaFuncAttributeMaxDynamicSharedMemorySize, DYN_SMEM);
    cudaFuncSetAttribute(gemm_mma<2>, cudaFuncAttributeMaxDynamicSharedMemorySize, DYN_SMEM);

    float*  qptr = nullptr; cudaGetSymbolAddress((void**)&qptr,  g_q);
    __half* qh   = nullptr; cudaGetSymbolAddress((void**)&qh,    g_q_hi);
    __half* ql   = nullptr; cudaGetSymbolAddress((void**)&ql,    g_q_lo);
    __half* xh   = nullptr; cudaGetSymbolAddress((void**)&xh,    g_x_hi);
    __half* xth  = nullptr; cudaGetSymbolAddress((void**)&xth,   g_xT_hi);
    __half* wh   = nullptr; cudaGetSymbolAddress((void**)&wh,    g_w_hi);
    __half* wl   = nullptr; cudaGetSymbolAddress((void**)&wl,    g_w_lo);
    float*  eptr = nullptr; cudaGetSymbolAddress((void**)&eptr,  g_ep);
    __half* ah   = nullptr; cudaGetSymbolAddress((void**)&ah,    g_a_hi);
    __half* al   = nullptr; cudaGetSymbolAddress((void**)&al,    g_a_lo);

    prep_x<<<dim3(HW / 32, CIN / 32, BATCH), dim3(32, 8)>>>(x);
    prep_w<<<(C1 * CIN + 255) / 256, 256>>>(convw);

    // proj: q = W x + b   (M=C1, N=HW, K=CIN); emits q fp32 + q hi/lo fp16
    gemm_mma<0><<<dim3(HW / BN, C1 / BM, BATCH), NTH, DYN_SMEM>>>(
        wh, wl, 0, CIN, xth, (size_t)HW * CIN, CIN,
        qptr, (size_t)C1 * HW, HW, CIN, 1, convb, 0, nullptr, qh, ql);

    // energy partials: e = q x^T  (M=C1, N=CIN, K=HW split 2)
    gemm_mma<1><<<dim3(CIN / BN, C1 / BM, BATCH * KSPLIT_E), NTH, DYN_SMEM>>>(
        qh, ql, (size_t)C1 * HW, HW, xh, (size_t)CIN * HW, HW,
        eptr, (size_t)C1 * CIN, CIN, HW / KSPLIT_E, KSPLIT_E,
        nullptr, 0, nullptr, nullptr, nullptr);

    softmax_rows<<<BATCH * C1, 128>>>();

    // out: gamma*(att x) + q  (M=C1, N=HW, K=CIN)
    gemm_mma<2><<<dim3(HW / BN, C1 / BM, BATCH), NTH, DYN_SMEM>>>(
        ah, al, (size_t)C1 * CIN, CIN, xth, (size_t)HW * CIN, CIN,
        out, (size_t)C1 * HW, HW, CIN, 1,
        qptr, (size_t)C1 * HW, gamma, nullptr, nullptr);
}

// round 9
// speedup vs baseline: 4.9183x; 1.4806x over previous
#include <cuda_runtime.h>
#include <cuda_fp16.h>
#include <stdint.h>
#include <math.h>

// Problem constants
#define BATCH 16
#define CIN   512
#define C1    256
#define HW    4096
#define INV_SQRT_HW (1.0f/64.0f)

// GEMM tiling
#define BM 128
#define BN 128
#define BK 32
#define NTH 256
#define SROW 40                 // padded row stride in halves (80 B)
#define NSTAGE 3

// SMEM stage layout (bytes)
#define TILE_B (BM * SROW * 2)  // 10240
#define T_A 0
#define T_B TILE_B
#define STAGE_B (2 * TILE_B)    // 20480
#define DYN_SMEM (NSTAGE * STAGE_B)  // 61440

#define KSPLIT_E 2

// Scratch (allocation-free rule: __device__ globals)
__device__ __align__(16) float  g_q   [(size_t)BATCH * C1 * HW];
__device__ __align__(16) __half g_q_hi[(size_t)BATCH * C1 * HW];
__device__ __align__(16) __half g_x_hi[(size_t)BATCH * CIN * HW];
__device__ __align__(16) __half g_xT_hi[(size_t)BATCH * HW * CIN];
__device__ __align__(16) __half g_w_hi[(size_t)C1 * CIN];
__device__ __align__(16) float  g_ep  [(size_t)BATCH * KSPLIT_E * C1 * CIN];
__device__ __align__(16) __half g_a_hi[(size_t)BATCH * C1 * CIN];

// ---------------- helpers ----------------
__device__ __forceinline__ uint32_t smem_u32(const void* p) {
    uint32_t a;
    asm("{ .reg .u64 t; cvta.to.shared.u64 t, %1; cvt.u32.u64 %0, t; }" : "=r"(a) : "l"(p));
    return a;
}
__device__ __forceinline__ void cpasync16(uint32_t dst, const void* src) {
    asm volatile("cp.async.cg.shared.global [%0], [%1], 16;" :: "r"(dst), "l"(src) : "memory");
}
#define CP_COMMIT() asm volatile("cp.async.commit_group;" ::: "memory")
#define CP_WAIT(n)  asm volatile("cp.async.wait_group %0;" :: "n"(n) : "memory")

__device__ __forceinline__ void mma16816(float* d, const uint32_t* a, uint32_t b0, uint32_t b1) {
    asm volatile(
        "mma.sync.aligned.m16n8k16.row.col.f32.f16.f16.f32 "
        "{%0,%1,%2,%3}, {%4,%5,%6,%7}, {%8,%9}, {%0,%1,%2,%3};"
        : "+f"(d[0]), "+f"(d[1]), "+f"(d[2]), "+f"(d[3])
        : "r"(a[0]), "r"(a[1]), "r"(a[2]), "r"(a[3]), "r"(b0), "r"(b1));
}
__device__ __forceinline__ void ldsm4(uint32_t* r, uint32_t addr) {
    asm volatile("ldmatrix.sync.aligned.m8n8.x4.shared.b16 {%0,%1,%2,%3}, [%4];"
        : "=r"(r[0]), "=r"(r[1]), "=r"(r[2]), "=r"(r[3]) : "r"(addr));
}

// ---------------------------------------------------------------------------
// prep_x: x fp32 -> x_hi (same layout) + xT_hi (transposed), fp16
// ---------------------------------------------------------------------------
__global__ __launch_bounds__(256) void prep_x(const float* __restrict__ x)
{
    __shared__ float t[32][33];
    const int b = blockIdx.z;
    const int n0 = blockIdx.x * 32, c0 = blockIdx.y * 32;
    const int tx = threadIdx.x, ty = threadIdx.y;   // (32, 8)
    const float* xs = x + (size_t)b * CIN * HW;
    __half* xh  = g_x_hi  + (size_t)b * CIN * HW;
    __half* xth = g_xT_hi + (size_t)b * HW * CIN;
    #pragma unroll
    for (int i = 0; i < 4; ++i) {
        float v = xs[(size_t)(c0 + ty + i * 8) * HW + n0 + tx];
        t[ty + i * 8][tx] = v;
        xh[(size_t)(c0 + ty + i * 8) * HW + n0 + tx] = __float2half_rn(v);
    }
    __syncthreads();
    #pragma unroll
    for (int i = 0; i < 4; ++i)
        xth[(size_t)(n0 + ty + i * 8) * CIN + c0 + tx] = __float2half_rn(t[tx][ty + i * 8]);
}

// prep_w: W fp32 -> fp16
__global__ __launch_bounds__(256) void prep_w(const float* __restrict__ w)
{
    int f = blockIdx.x * 256 + threadIdx.x;
    if (f < C1 * CIN) g_w_hi[f] = __float2half_rn(w[f]);
}

// ---------------------------------------------------------------------------
// NT GEMM (fp16 single-pass, 3-stage cp.async pipeline, ldmatrix frags):
//   D[m][n] = sum_k A[m][k] * B[n][k]
// EPI 0: +bias, also emit fp16   EPI 1: raw   EPI 2: gamma*acc + res
// grid: (N/BN, M/BM, BATCH*zdiv)
// ---------------------------------------------------------------------------
template<int EPI>
__global__ __launch_bounds__(NTH, 2) void gemm_mma(
    const __half* __restrict__ A, size_t sA, int lda,
    const __half* __restrict__ B, size_t sB, int ldb,
    float* __restrict__ C, size_t sC, int ldc,
    int K, int zdiv,
    const float* __restrict__ aux, size_t sAux,
    const float* __restrict__ gamma,
    __half* __restrict__ outHalf)
{
    extern __shared__ char dyn[];
    const uint32_t sbase = smem_u32(dyn);

    const int tid  = threadIdx.x;
    const int z    = blockIdx.z;
    const int b    = z / zdiv;
    const int kbase = (z % zdiv) * K;
    const int m0 = blockIdx.y * BM;
    const int n0 = blockIdx.x * BN;

    const __half* Ab = A + (size_t)b * sA + kbase;
    const __half* Bb = B + (size_t)b * sB + kbase;
    float*        Cb = C + (size_t)z * sC;

    const int wid = tid >> 5, lane = tid & 31;
    const int wm = (wid & 3) * 32;
    const int wn = (wid >> 2) * 64;
    const int g  = lane >> 2;
    const int t2 = (lane & 3) * 2;

    // ldmatrix per-lane row offsets (in halves)
    const int l7  = lane & 7;
    const int t8  = (lane >> 3) & 1;
    const int t16 = lane >> 4;
    int aoff[2], boff[4];
    #pragma unroll
    for (int mi = 0; mi < 2; ++mi)
        aoff[mi] = (wm + mi * 16 + t8 * 8 + l7) * SROW + t16 * 8;
    #pragma unroll
    for (int nb = 0; nb < 4; ++nb)
        boff[nb] = (wn + nb * 16 + t16 * 8 + l7) * SROW + t8 * 8;

    // per-thread fill coords: 2 chunks of 16B per tile per stage
    const int fr0 = tid >> 2, fc0 = tid & 3;
    const int fr1 = (tid + NTH) >> 2, fc1 = (tid + NTH) & 3;

    float acc[2][8][4];
    #pragma unroll
    for (int mi = 0; mi < 2; ++mi)
        #pragma unroll
        for (int ni = 0; ni < 8; ++ni)
            #pragma unroll
            for (int r = 0; r < 4; ++r) acc[mi][ni][r] = 0.f;

    const int nst = K / BK;

#define ISSUE(s) do {                                                              \
        const uint32_t sb_ = sbase + ((s) % NSTAGE) * STAGE_B;                     \
        const int k0_ = (s) * BK;                                                  \
        cpasync16(sb_ + T_A + fr0 * 80 + fc0 * 16, Ab + (size_t)(m0 + fr0) * lda + k0_ + fc0 * 8); \
        cpasync16(sb_ + T_A + fr1 * 80 + fc1 * 16, Ab + (size_t)(m0 + fr1) * lda + k0_ + fc1 * 8); \
        cpasync16(sb_ + T_B + fr0 * 80 + fc0 * 16, Bb + (size_t)(n0 + fr0) * ldb + k0_ + fc0 * 8); \
        cpasync16(sb_ + T_B + fr1 * 80 + fc1 * 16, Bb + (size_t)(n0 + fr1) * ldb + k0_ + fc1 * 8); \
        CP_COMMIT();                                                               \
    } while (0)

    // prologue: 2 stages in flight
    ISSUE(0);
    ISSUE(1);
    for (int s = 0; s < nst; ++s) {
        if (s + 1 < nst) CP_WAIT(1); else CP_WAIT(0);
        __syncthreads();                 // stage s ready; all warps done reading stage s-1
        if (s + 2 < nst) ISSUE(s + 2);   // refill buffer (s+2)%3

        const uint32_t stg = sbase + (s % NSTAGE) * STAGE_B;
        const uint32_t aB = stg + T_A;
        const uint32_t bB = stg + T_B;

        #pragma unroll
        for (int kk = 0; kk < BK; kk += 16) {
            uint32_t ah[2][4];
            ldsm4(ah[0], aB + 2 * (aoff[0] + kk));
            ldsm4(ah[1], aB + 2 * (aoff[1] + kk));
            #pragma unroll
            for (int nb = 0; nb < 4; ++nb) {
                uint32_t bb[4];
                ldsm4(bb, bB + 2 * (boff[nb] + kk));
                #pragma unroll
                for (int mi = 0; mi < 2; ++mi) {
                    mma16816(acc[mi][nb * 2 + 0], ah[mi], bb[0], bb[1]);
                    mma16816(acc[mi][nb * 2 + 1], ah[mi], bb[2], bb[3]);
                }
            }
        }
    }
#undef ISSUE

    // ---- epilogue ----
    const float gm = (EPI == 2) ? __ldg(gamma) : 0.f;
    const float* Rb = (EPI == 2) ? aux + (size_t)b * sAux : aux;
    __half* oh = (EPI == 0) ? outHalf + (size_t)z * sC : nullptr;
    #pragma unroll
    for (int mi = 0; mi < 2; ++mi) {
        int row = m0 + wm + mi * 16 + g;
        #pragma unroll
        for (int ni = 0; ni < 8; ++ni) {
            int col = n0 + wn + ni * 8 + t2;
            float2 v0 = make_float2(acc[mi][ni][0], acc[mi][ni][1]);
            float2 v1 = make_float2(acc[mi][ni][2], acc[mi][ni][3]);
            if (EPI == 0) {
                float b0 = Rb[row], b1 = Rb[row + 8];
                v0.x += b0; v0.y += b0;
                v1.x += b1; v1.y += b1;
            } else if (EPI == 2) {
                float2 q0 = *reinterpret_cast<const float2*>(&Rb[(size_t)row * ldc + col]);
                float2 q1 = *reinterpret_cast<const float2*>(&Rb[(size_t)(row + 8) * ldc + col]);
                v0.x = gm * v0.x + q0.x; v0.y = gm * v0.y + q0.y;
                v1.x = gm * v1.x + q1.x; v1.y = gm * v1.y + q1.y;
            }
            *reinterpret_cast<float2*>(&Cb[(size_t)row * ldc + col]) = v0;
            *reinterpret_cast<float2*>(&Cb[(size_t)(row + 8) * ldc + col]) = v1;
            if (EPI == 0) {
                *reinterpret_cast<__half2*>(&oh[(size_t)row * ldc + col]) =
                    __halves2half2(__float2half_rn(v0.x), __float2half_rn(v0.y));
                *reinterpret_cast<__half2*>(&oh[(size_t)(row + 8) * ldc + col]) =
                    __halves2half2(__float2half_rn(v1.x), __float2half_rn(v1.y));
            }
        }
    }
}

// ---------------------------------------------------------------------------
// Softmax: reduce split-K partials, scale, softmax, emit att fp16
// ---------------------------------------------------------------------------
__global__ __launch_bounds__(128) void softmax_rows()
{
    const int row = blockIdx.x;              // b*C1 + m
    const int b   = row / C1;
    const int m   = row % C1;
    const int tid = threadIdx.x;
    const size_t p0 = ((size_t)b * KSPLIT_E) * C1 * CIN + (size_t)m * CIN + tid * 4;
    const size_t pk = (size_t)C1 * CIN;

    float4 a0 = *reinterpret_cast<const float4*>(&g_ep[p0]);
    float4 a1 = *reinterpret_cast<const float4*>(&g_ep[p0 + pk]);
    float v[4];
    v[0] = (a0.x + a1.x) * INV_SQRT_HW;
    v[1] = (a0.y + a1.y) * INV_SQRT_HW;
    v[2] = (a0.z + a1.z) * INV_SQRT_HW;
    v[3] = (a0.w + a1.w) * INV_SQRT_HW;

    float mx = fmaxf(fmaxf(v[0], v[1]), fmaxf(v[2], v[3]));
    #pragma unroll
    for (int off = 16; off > 0; off >>= 1)
        mx = fmaxf(mx, __shfl_xor_sync(0xffffffffu, mx, off));
    __shared__ float red[4];
    const int lane = tid & 31, wid = tid >> 5;
    if (lane == 0) red[wid] = mx;
    __syncthreads();
    mx = fmaxf(fmaxf(red[0], red[1]), fmaxf(red[2], red[3]));
    __syncthreads();

    float e[4], s = 0.f;
    #pragma unroll
    for (int i = 0; i < 4; ++i) { e[i] = expf(v[i] - mx); s += e[i]; }
    #pragma unroll
    for (int off = 16; off > 0; off >>= 1)
        s += __shfl_xor_sync(0xffffffffu, s, off);
    if (lane == 0) red[wid] = s;
    __syncthreads();
    s = red[0] + red[1] + red[2] + red[3];
    const float inv = 1.0f / s;

    const size_t ob = (size_t)row * CIN + tid * 4;
    *reinterpret_cast<__half2*>(&g_a_hi[ob]) =
        __halves2half2(__float2half_rn(e[0] * inv), __float2half_rn(e[1] * inv));
    *reinterpret_cast<__half2*>(&g_a_hi[ob + 2]) =
        __halves2half2(__float2half_rn(e[2] * inv), __float2half_rn(e[3] * inv));
}

// ---------------------------------------------------------------------------
extern "C" void kernel_launch(void* const* d_in, const int* in_sizes, int n_in,
                              void* d_out, int out_size)
{
    const float* x     = (const float*)d_in[0];  // (16,512,64,64)
    const float* convw = (const float*)d_in[1];  // (256,512,1,1)
    const float* convb = (const float*)d_in[2];  // (256,)
    const float* gamma = (const float*)d_in[3];  // (1,)
    float* out = (float*)d_out;                  // (16,256,64,64)

    cudaFuncSetAttribute(gemm_mma<0>, cudaFuncAttributeMaxDynamicSharedMemorySize, DYN_SMEM);
    cudaFuncSetAttribute(gemm_mma<1>, cudaFuncAttributeMaxDynamicSharedMemorySize, DYN_SMEM);
    cudaFuncSetAttribute(gemm_mma<2>, cudaFuncAttributeMaxDynamicSharedMemorySize, DYN_SMEM);

    float*  qptr = nullptr; cudaGetSymbolAddress((void**)&qptr,  g_q);
    __half* qh   = nullptr; cudaGetSymbolAddress((void**)&qh,    g_q_hi);
    __half* xh   = nullptr; cudaGetSymbolAddress((void**)&xh,    g_x_hi);
    __half* xth  = nullptr; cudaGetSymbolAddress((void**)&xth,   g_xT_hi);
    __half* wh   = nullptr; cudaGetSymbolAddress((void**)&wh,    g_w_hi);
    float*  eptr = nullptr; cudaGetSymbolAddress((void**)&eptr,  g_ep);
    __half* ah   = nullptr; cudaGetSymbolAddress((void**)&ah,    g_a_hi);

    prep_x<<<dim3(HW / 32, CIN / 32, BATCH), dim3(32, 8)>>>(x);
    prep_w<<<(C1 * CIN + 255) / 256, 256>>>(convw);

    // proj: q = W x + b   (M=C1, N=HW, K=CIN); emits q fp32 + q fp16
    gemm_mma<0><<<dim3(HW / BN, C1 / BM, BATCH), NTH, DYN_SMEM>>>(
        wh, 0, CIN, xth, (size_t)HW * CIN, CIN,
        qptr, (size_t)C1 * HW, HW, CIN, 1, convb, 0, nullptr, qh);

    // energy partials: e = q x^T  (M=C1, N=CIN, K=HW split 2)
    gemm_mma<1><<<dim3(CIN / BN, C1 / BM, BATCH * KSPLIT_E), NTH, DYN_SMEM>>>(
        qh, (size_t)C1 * HW, HW, xh, (size_t)CIN * HW, HW,
        eptr, (size_t)C1 * CIN, CIN, HW / KSPLIT_E, KSPLIT_E,
        nullptr, 0, nullptr, nullptr);

    softmax_rows<<<BATCH * C1, 128>>>();

    // out: gamma*(att x) + q  (M=C1, N=HW, K=CIN)
    gemm_mma<2><<<dim3(HW / BN, C1 / BM, BATCH), NTH, DYN_SMEM>>>(
        ah, (size_t)C1 * CIN, CIN, xth, (size_t)HW * CIN, CIN,
        out, (size_t)C1 * HW, HW, CIN, 1,
        qptr, (size_t)C1 * HW, gamma, nullptr);
}